// round 3
// baseline (speedup 1.0000x reference)
#include <cuda_runtime.h>
#include <cuda_bf16.h>
#include <cstdint>

typedef unsigned long long ull;

// Problem constants (fixed by the dataset)
#define MAXN 50000
#define MAXE 800000
#define IN_DIM 128
#define NUM_HEADS 8
#define HEAD_DIM 16
#define HD 128              // NUM_HEADS*HEAD_DIM

// ---- QKV GEMM tiling ----
#define QN 128              // nodes per block tile
#define HS_STRIDE 132       // padded k-stride for h tile (kills bank conflicts)
#define SMEM_HS_FLOATS (QN * HS_STRIDE)
#define SMEM_WS_FLOATS (IN_DIM * HD)
#define QKV_SMEM_BYTES ((SMEM_HS_FLOATS + SMEM_WS_FLOATS) * 4)

// ---- scratch (static device arrays; no allocation allowed) ----
__device__ float g_Q[(size_t)MAXN * HD];   // pre-scaled by 0.25
__device__ float g_K[(size_t)MAXN * HD];
__device__ float g_V[(size_t)MAXN * HD];
__device__ int   g_ints[2 * MAXN];         // [0,MAXN)=deg/hist, [MAXN,2MAXN)=cnt
__device__ int   g_off[MAXN + 1];
__device__ int   g_chsum[64];
__device__ int   g_src_sorted[MAXE];

// ---------------------------------------------------------------------------
// Kernel 1: QKV projection, tiled SGEMM with packed f32x2 FMA.
// grid = (ceil(N/128), 3); blockIdx.y selects {Q,K,V}.
// Block tile: 128 nodes x 128 cols. 256 threads, each owns 8 nodes x 8 cols.
// Accumulator pairs run over adjacent COLUMNS, so W loads (ld.shared.v2.b64)
// give packed operands directly; h is a scalar broadcast packed via mov.b64.
// Per thread-k: 8 scalar LDS(h) + 2 vec LDS(W) + 8 mov + 32 fma.rn.f32x2.
// ---------------------------------------------------------------------------
__global__ __launch_bounds__(256) void qkv_kernel(
    const float* __restrict__ h,
    const float* __restrict__ Wq, const float* __restrict__ Wk, const float* __restrict__ Wv,
    const float* __restrict__ bq, const float* __restrict__ bk, const float* __restrict__ bv,
    int N)
{
    extern __shared__ float smem[];
    float* hs = smem;                    // [128 nodes][132]
    float* Ws = smem + SMEM_HS_FLOATS;   // [128 k][128 cols]

    const int m  = blockIdx.y;           // 0=Q, 1=K, 2=V
    const float* W = (m == 0) ? Wq : ((m == 1) ? Wk : Wv);
    const float* b = (m == 0) ? bq : ((m == 1) ? bk : bv);
    float* outbuf  = (m == 0) ? g_Q : ((m == 1) ? g_K : g_V);
    const float mul = (m == 0) ? 0.25f : 1.0f;

    const int n0  = blockIdx.x * QN;
    const int tid = threadIdx.x;

    // Stage W tile [k][c], same layout as global -> coalesced float4 copy
    for (int i = tid * 4; i < IN_DIM * HD; i += 256 * 4)
        *reinterpret_cast<float4*>(&Ws[i]) = *reinterpret_cast<const float4*>(&W[i]);

    // Stage h tile untransposed: hs[n][k], padded stride
    for (int idx = tid * 4; idx < QN * IN_DIM; idx += 256 * 4) {
        int n = idx >> 7;
        int k = idx & 127;
        float4 v = make_float4(0.f, 0.f, 0.f, 0.f);
        if (n0 + n < N) v = *reinterpret_cast<const float4*>(&h[(size_t)(n0 + n) * IN_DIM + k]);
        *reinterpret_cast<float4*>(&hs[n * HS_STRIDE + k]) = v;
    }
    __syncthreads();

    const int cg = tid & 15;   // col group: cols [8*cg, 8*cg+8)
    const int ng = tid >> 4;   // node group: nodes [8*ng, 8*ng+8)
    const int col0 = cg * 8;

    const unsigned sbase = (unsigned)__cvta_generic_to_shared(smem);
    const unsigned hb = sbase + (unsigned)(ng * 8 * HS_STRIDE) * 4u;           // + j*528 + k*4
    const unsigned wb = sbase + (unsigned)(SMEM_HS_FLOATS + col0) * 4u;        // + k*512

    ull acc[32];
#pragma unroll
    for (int i = 0; i < 32; i++) acc[i] = 0ull;

#pragma unroll 4
    for (int k = 0; k < IN_DIM; k++) {
        ull w01, w23, w45, w67;
        asm volatile("ld.shared.v2.b64 {%0,%1}, [%2];"
                     : "=l"(w01), "=l"(w23) : "r"(wb + (unsigned)k * 512u));
        asm volatile("ld.shared.v2.b64 {%0,%1}, [%2];"
                     : "=l"(w45), "=l"(w67) : "r"(wb + (unsigned)k * 512u + 16u));

#define FMA2(a, hp, wp) asm("fma.rn.f32x2 %0, %1, %2, %0;" : "+l"(a) : "l"(hp), "l"(wp))
#pragma unroll
        for (int j = 0; j < 8; j++) {
            unsigned hu;
            asm volatile("ld.shared.b32 %0, [%1];"
                         : "=r"(hu) : "r"(hb + (unsigned)j * (HS_STRIDE * 4) + (unsigned)k * 4u));
            ull hp;
            asm("mov.b64 %0, {%1,%1};" : "=l"(hp) : "r"(hu));
            FMA2(acc[j * 4 + 0], hp, w01);
            FMA2(acc[j * 4 + 1], hp, w23);
            FMA2(acc[j * 4 + 2], hp, w45);
            FMA2(acc[j * 4 + 3], hp, w67);
        }
#undef FMA2
    }

    const float4 bj0 = *reinterpret_cast<const float4*>(&b[col0]);
    const float4 bj1 = *reinterpret_cast<const float4*>(&b[col0 + 4]);

#pragma unroll
    for (int j = 0; j < 8; j++) {
        int node = n0 + ng * 8 + j;
        if (node < N) {
            float r[8];
#pragma unroll
            for (int p = 0; p < 4; p++) {
                unsigned lo, hi;
                asm("mov.b64 {%0,%1}, %2;" : "=r"(lo), "=r"(hi) : "l"(acc[j * 4 + p]));
                r[2 * p]     = __uint_as_float(lo);
                r[2 * p + 1] = __uint_as_float(hi);
            }
            float4 o0, o1;
            o0.x = (r[0] + bj0.x) * mul; o0.y = (r[1] + bj0.y) * mul;
            o0.z = (r[2] + bj0.z) * mul; o0.w = (r[3] + bj0.w) * mul;
            o1.x = (r[4] + bj1.x) * mul; o1.y = (r[5] + bj1.y) * mul;
            o1.z = (r[6] + bj1.z) * mul; o1.w = (r[7] + bj1.w) * mul;
            float* op = &outbuf[(size_t)node * HD + col0];
            *reinterpret_cast<float4*>(op)     = o0;
            *reinterpret_cast<float4*>(op + 4) = o1;
        }
    }
}

// ---------------------------------------------------------------------------
// CSR construction: histogram -> scan (3 stages) -> scatter
// ---------------------------------------------------------------------------
__global__ void hist_kernel(const int* __restrict__ dst, int E)
{
    int i = blockIdx.x * blockDim.x + threadIdx.x;
    if (i < E) atomicAdd(&g_ints[dst[i]], 1);
}

__global__ __launch_bounds__(1024) void scanA_kernel(int N)
{
    __shared__ int s[1024];
    const int t = threadIdx.x;
    const int i = blockIdx.x * 1024 + t;
    int x = (i < N) ? g_ints[i] : 0;
    s[t] = x;
    __syncthreads();
#pragma unroll
    for (int d = 1; d < 1024; d <<= 1) {
        int v = (t >= d) ? s[t - d] : 0;
        __syncthreads();
        s[t] += v;
        __syncthreads();
    }
    if (i < N) g_off[i] = s[t] - x;        // exclusive within chunk
    if (t == 1023) g_chsum[blockIdx.x] = s[t];
}

__global__ void scanB_kernel(int nch, int N)
{
    if (threadIdx.x == 0) {
        int acc = 0;
        for (int b = 0; b < nch; b++) {
            int v = g_chsum[b];
            g_chsum[b] = acc;
            acc += v;
        }
        g_off[N] = acc;   // == E
    }
}

__global__ void scanC_kernel(int N)
{
    int i = blockIdx.x * blockDim.x + threadIdx.x;
    if (i < N) g_off[i] += g_chsum[i >> 10];
}

__global__ void scatter_kernel(const int* __restrict__ src, const int* __restrict__ dst, int E)
{
    int i = blockIdx.x * blockDim.x + threadIdx.x;
    if (i < E) {
        int d = dst[i];
        int p = g_off[d] + atomicAdd(&g_ints[MAXN + d], 1);
        g_src_sorted[p] = src[i];
    }
}

// ---------------------------------------------------------------------------
// Kernel 3: warp-per-dst attention. Lane l owns dims [4l,4l+4) => head l>>2.
// Q loaded once per node; wV and z accumulated in registers; normalize inline.
// No atomics, no output memset, no div pass.
// ---------------------------------------------------------------------------
__global__ void attn_kernel(float* __restrict__ out, int N)
{
    const int lane = threadIdx.x & 31;
    const int w = (blockIdx.x * blockDim.x + threadIdx.x) >> 5;
    if (w >= N) return;

    const int beg = g_off[w];
    const int end = g_off[w + 1];

    const float4 q = *reinterpret_cast<const float4*>(g_Q + (size_t)w * HD + lane * 4);

    float4 av = make_float4(0.f, 0.f, 0.f, 0.f);
    float z = 0.f;

    int s = (beg < end) ? g_src_sorted[beg] : 0;
    for (int e = beg; e < end; e++) {
        int snext = (e + 1 < end) ? g_src_sorted[e + 1] : 0;

        const float4 k = *reinterpret_cast<const float4*>(g_K + (size_t)s * HD + lane * 4);
        float sc = q.x * k.x + q.y * k.y + q.z * k.z + q.w * k.w;
        sc += __shfl_xor_sync(0xffffffffu, sc, 1);
        sc += __shfl_xor_sync(0xffffffffu, sc, 2);
        sc = __expf(fminf(fmaxf(sc, -5.f), 5.f));

        const float4 v = *reinterpret_cast<const float4*>(g_V + (size_t)s * HD + lane * 4);
        av.x = fmaf(v.x, sc, av.x);
        av.y = fmaf(v.y, sc, av.y);
        av.z = fmaf(v.z, sc, av.z);
        av.w = fmaf(v.w, sc, av.w);
        if ((lane & 3) == 0) z += sc;

        s = snext;
    }

    z = __shfl_sync(0xffffffffu, z, lane & ~3);
    const float inv = 1.f / z;

    float4 o;
    o.x = av.x * inv; o.y = av.y * inv; o.z = av.z * inv; o.w = av.w * inv;
    *reinterpret_cast<float4*>(out + (size_t)w * HD + lane * 4) = o;
}

// ---------------------------------------------------------------------------
extern "C" void kernel_launch(void* const* d_in, const int* in_sizes, int n_in,
                              void* d_out, int out_size)
{
    const float* h  = (const float*)d_in[0];
    const int* src  = (const int*)d_in[1];
    const int* dst  = (const int*)d_in[2];
    const float* Wq = (const float*)d_in[3];
    const float* Wk = (const float*)d_in[4];
    const float* Wv = (const float*)d_in[5];
    const float* bq = (const float*)d_in[6];
    const float* bk = (const float*)d_in[7];
    const float* bv = (const float*)d_in[8];
    float* out = (float*)d_out;

    const int N = in_sizes[0] / IN_DIM;
    const int E = in_sizes[1];

    static bool attr_set = false;
    if (!attr_set) {
        cudaFuncSetAttribute(qkv_kernel, cudaFuncAttributeMaxDynamicSharedMemorySize,
                             QKV_SMEM_BYTES);
        attr_set = true;
    }

    // Zero hist + cnt in one memset
    void* iptr = nullptr;
    cudaGetSymbolAddress(&iptr, g_ints);
    cudaMemsetAsync(iptr, 0, 2 * MAXN * sizeof(int));

    const int eb = (E + 255) / 256;
    const int nch = (N + 1023) / 1024;

    // CSR build
    hist_kernel<<<eb, 256>>>(dst, E);
    scanA_kernel<<<nch, 1024>>>(N);
    scanB_kernel<<<1, 32>>>(nch, N);
    scanC_kernel<<<(N + 255) / 256, 256>>>(N);
    scatter_kernel<<<eb, 256>>>(src, dst, E);

    // QKV projection
    dim3 gemm_grid((N + QN - 1) / QN, 3);
    qkv_kernel<<<gemm_grid, 256, QKV_SMEM_BYTES>>>(h, Wq, Wk, Wv, bq, bk, bv, N);

    // Attention (warp per dst node)
    attn_kernel<<<(N * 32 + 255) / 256, 256>>>(out, N);
}

// round 4
// speedup vs baseline: 1.0068x; 1.0068x over previous
#include <cuda_runtime.h>
#include <cuda_bf16.h>
#include <cstdint>

typedef unsigned long long ull;

// Problem constants (fixed by the dataset)
#define MAXN 50000
#define MAXE 800000
#define IN_DIM 128
#define NUM_HEADS 8
#define HEAD_DIM 16
#define HD 128              // NUM_HEADS*HEAD_DIM

// ---- QKV GEMM tiling ----
#define QN 128              // nodes per block tile
#define HS_STRIDE 132       // padded k-stride for h tile (kills bank conflicts)
#define SMEM_HS_FLOATS (QN * HS_STRIDE)
#define SMEM_WS_FLOATS (IN_DIM * HD)
#define QKV_SMEM_BYTES ((SMEM_HS_FLOATS + SMEM_WS_FLOATS) * 4)

// ---- scratch (static device arrays; no allocation allowed) ----
__device__ float g_Q[(size_t)MAXN * HD];   // pre-scaled by 0.25
__device__ float g_K[(size_t)MAXN * HD];
__device__ float g_V[(size_t)MAXN * HD];
__device__ int   g_deg[MAXN];
__device__ int   g_off[MAXN];              // after scatter: g_off[d] = segment END of d
__device__ int   g_src_sorted[MAXE];

// ---------------------------------------------------------------------------
// Kernel 1: QKV projection, tiled SGEMM with packed f32x2 FMA.
// grid = (ceil(N/128), 3); blockIdx.y selects {Q,K,V}.
// Block tile: 128 nodes x 128 cols. 256 threads, each owns 8 nodes x 8 cols.
// ---------------------------------------------------------------------------
__global__ __launch_bounds__(256) void qkv_kernel(
    const float* __restrict__ h,
    const float* __restrict__ Wq, const float* __restrict__ Wk, const float* __restrict__ Wv,
    const float* __restrict__ bq, const float* __restrict__ bk, const float* __restrict__ bv,
    int N)
{
    extern __shared__ float smem[];
    float* hs = smem;                    // [128 nodes][132]
    float* Ws = smem + SMEM_HS_FLOATS;   // [128 k][128 cols]

    const int m  = blockIdx.y;           // 0=Q, 1=K, 2=V
    const float* W = (m == 0) ? Wq : ((m == 1) ? Wk : Wv);
    const float* b = (m == 0) ? bq : ((m == 1) ? bk : bv);
    float* outbuf  = (m == 0) ? g_Q : ((m == 1) ? g_K : g_V);
    const float mul = (m == 0) ? 0.25f : 1.0f;

    const int n0  = blockIdx.x * QN;
    const int tid = threadIdx.x;

    // Stage W tile [k][c] (coalesced float4 copy)
    for (int i = tid * 4; i < IN_DIM * HD; i += 256 * 4)
        *reinterpret_cast<float4*>(&Ws[i]) = *reinterpret_cast<const float4*>(&W[i]);

    // Stage h tile untransposed: hs[n][k], padded stride
    for (int idx = tid * 4; idx < QN * IN_DIM; idx += 256 * 4) {
        int n = idx >> 7;
        int k = idx & 127;
        float4 v = make_float4(0.f, 0.f, 0.f, 0.f);
        if (n0 + n < N) v = *reinterpret_cast<const float4*>(&h[(size_t)(n0 + n) * IN_DIM + k]);
        *reinterpret_cast<float4*>(&hs[n * HS_STRIDE + k]) = v;
    }
    __syncthreads();

    const int cg = tid & 15;   // col group: cols [8*cg, 8*cg+8)
    const int ng = tid >> 4;   // node group: nodes [8*ng, 8*ng+8)
    const int col0 = cg * 8;

    const unsigned sbase = (unsigned)__cvta_generic_to_shared(smem);
    const unsigned hb = sbase + (unsigned)(ng * 8 * HS_STRIDE) * 4u;
    const unsigned wb = sbase + (unsigned)(SMEM_HS_FLOATS + col0) * 4u;

    ull acc[32];
#pragma unroll
    for (int i = 0; i < 32; i++) acc[i] = 0ull;

#pragma unroll 4
    for (int k = 0; k < IN_DIM; k++) {
        ull w01, w23, w45, w67;
        asm volatile("ld.shared.v2.b64 {%0,%1}, [%2];"
                     : "=l"(w01), "=l"(w23) : "r"(wb + (unsigned)k * 512u));
        asm volatile("ld.shared.v2.b64 {%0,%1}, [%2];"
                     : "=l"(w45), "=l"(w67) : "r"(wb + (unsigned)k * 512u + 16u));

#define FMA2(a, hp, wp) asm("fma.rn.f32x2 %0, %1, %2, %0;" : "+l"(a) : "l"(hp), "l"(wp))
#pragma unroll
        for (int j = 0; j < 8; j++) {
            unsigned hu;
            asm volatile("ld.shared.b32 %0, [%1];"
                         : "=r"(hu) : "r"(hb + (unsigned)j * (HS_STRIDE * 4) + (unsigned)k * 4u));
            ull hp;
            asm("mov.b64 %0, {%1,%1};" : "=l"(hp) : "r"(hu));
            FMA2(acc[j * 4 + 0], hp, w01);
            FMA2(acc[j * 4 + 1], hp, w23);
            FMA2(acc[j * 4 + 2], hp, w45);
            FMA2(acc[j * 4 + 3], hp, w67);
        }
#undef FMA2
    }

    const float4 bj0 = *reinterpret_cast<const float4*>(&b[col0]);
    const float4 bj1 = *reinterpret_cast<const float4*>(&b[col0 + 4]);

#pragma unroll
    for (int j = 0; j < 8; j++) {
        int node = n0 + ng * 8 + j;
        if (node < N) {
            float r[8];
#pragma unroll
            for (int p = 0; p < 4; p++) {
                unsigned lo, hi;
                asm("mov.b64 {%0,%1}, %2;" : "=r"(lo), "=r"(hi) : "l"(acc[j * 4 + p]));
                r[2 * p]     = __uint_as_float(lo);
                r[2 * p + 1] = __uint_as_float(hi);
            }
            float4 o0, o1;
            o0.x = (r[0] + bj0.x) * mul; o0.y = (r[1] + bj0.y) * mul;
            o0.z = (r[2] + bj0.z) * mul; o0.w = (r[3] + bj0.w) * mul;
            o1.x = (r[4] + bj1.x) * mul; o1.y = (r[5] + bj1.y) * mul;
            o1.z = (r[6] + bj1.z) * mul; o1.w = (r[7] + bj1.w) * mul;
            float* op = &outbuf[(size_t)node * HD + col0];
            *reinterpret_cast<float4*>(op)     = o0;
            *reinterpret_cast<float4*>(op + 4) = o1;
        }
    }
}

// ---------------------------------------------------------------------------
// CSR build: hist -> single-block scan -> scatter (atomic bump on g_off)
// ---------------------------------------------------------------------------
__global__ void hist_kernel(const int* __restrict__ dst, int E)
{
    int i = blockIdx.x * blockDim.x + threadIdx.x;
    if (i < E) atomicAdd(&g_deg[dst[i]], 1);
}

// Single-block exclusive scan over g_deg -> g_off. shfl warp scans + carry.
__global__ __launch_bounds__(1024) void scan_kernel(int N)
{
    __shared__ int warp_sums[32];
    __shared__ int s_carry;
    const int t = threadIdx.x;
    const int lane = t & 31, wid = t >> 5;
    if (t == 0) s_carry = 0;
    __syncthreads();

    for (int base = 0; base < N; base += 1024) {
        int i = base + t;
        int x = (i < N) ? g_deg[i] : 0;
        int inc = x;
#pragma unroll
        for (int d = 1; d < 32; d <<= 1) {
            int v = __shfl_up_sync(0xffffffffu, inc, d);
            if (lane >= d) inc += v;
        }
        if (lane == 31) warp_sums[wid] = inc;
        __syncthreads();
        if (wid == 0) {
            int ws = warp_sums[lane];
#pragma unroll
            for (int d = 1; d < 32; d <<= 1) {
                int v = __shfl_up_sync(0xffffffffu, ws, d);
                if (lane >= d) ws += v;
            }
            warp_sums[lane] = ws;   // inclusive over warp totals
        }
        __syncthreads();
        int warp_off = (wid > 0) ? warp_sums[wid - 1] : 0;
        if (i < N) g_off[i] = s_carry + warp_off + inc - x;   // exclusive
        int block_total = warp_sums[31];
        __syncthreads();
        if (t == 0) s_carry += block_total;
        __syncthreads();
    }
}

__global__ void scatter_kernel(const int* __restrict__ src, const int* __restrict__ dst, int E)
{
    int i = blockIdx.x * blockDim.x + threadIdx.x;
    if (i < E) {
        int d = dst[i];
        int p = atomicAdd(&g_off[d], 1);    // post: g_off[d] = end of segment d
        g_src_sorted[p] = src[i];
    }
}

// ---------------------------------------------------------------------------
// Kernel 3: warp-per-dst attention, unroll-2 for MLP.
// Lane l owns dims [4l,4l+4) => head l>>2.
// Segment bounds: beg = (w==0) ? 0 : g_off[w-1], end = g_off[w].
// ---------------------------------------------------------------------------
__global__ void attn_kernel(float* __restrict__ out, int N)
{
    const int lane = threadIdx.x & 31;
    const int w = (blockIdx.x * blockDim.x + threadIdx.x) >> 5;
    if (w >= N) return;

    const int beg = (w == 0) ? 0 : __ldg(&g_off[w - 1]);
    const int end = __ldg(&g_off[w]);

    const float4 q = *reinterpret_cast<const float4*>(g_Q + (size_t)w * HD + lane * 4);

    float4 av = make_float4(0.f, 0.f, 0.f, 0.f);
    float z = 0.f;

    int e = beg;
    for (; e + 2 <= end; e += 2) {
        const int s0 = __ldg(&g_src_sorted[e]);
        const int s1 = __ldg(&g_src_sorted[e + 1]);

        const float4 k0 = *reinterpret_cast<const float4*>(g_K + (size_t)s0 * HD + lane * 4);
        const float4 k1 = *reinterpret_cast<const float4*>(g_K + (size_t)s1 * HD + lane * 4);
        const float4 v0 = *reinterpret_cast<const float4*>(g_V + (size_t)s0 * HD + lane * 4);
        const float4 v1 = *reinterpret_cast<const float4*>(g_V + (size_t)s1 * HD + lane * 4);

        float sc0 = q.x * k0.x + q.y * k0.y + q.z * k0.z + q.w * k0.w;
        float sc1 = q.x * k1.x + q.y * k1.y + q.z * k1.z + q.w * k1.w;
        sc0 += __shfl_xor_sync(0xffffffffu, sc0, 1);
        sc1 += __shfl_xor_sync(0xffffffffu, sc1, 1);
        sc0 += __shfl_xor_sync(0xffffffffu, sc0, 2);
        sc1 += __shfl_xor_sync(0xffffffffu, sc1, 2);
        sc0 = __expf(fminf(fmaxf(sc0, -5.f), 5.f));
        sc1 = __expf(fminf(fmaxf(sc1, -5.f), 5.f));

        av.x = fmaf(v0.x, sc0, av.x); av.y = fmaf(v0.y, sc0, av.y);
        av.z = fmaf(v0.z, sc0, av.z); av.w = fmaf(v0.w, sc0, av.w);
        av.x = fmaf(v1.x, sc1, av.x); av.y = fmaf(v1.y, sc1, av.y);
        av.z = fmaf(v1.z, sc1, av.z); av.w = fmaf(v1.w, sc1, av.w);
        if ((lane & 3) == 0) z += sc0 + sc1;
    }
    if (e < end) {
        const int s0 = __ldg(&g_src_sorted[e]);
        const float4 k0 = *reinterpret_cast<const float4*>(g_K + (size_t)s0 * HD + lane * 4);
        float sc0 = q.x * k0.x + q.y * k0.y + q.z * k0.z + q.w * k0.w;
        sc0 += __shfl_xor_sync(0xffffffffu, sc0, 1);
        sc0 += __shfl_xor_sync(0xffffffffu, sc0, 2);
        sc0 = __expf(fminf(fmaxf(sc0, -5.f), 5.f));
        const float4 v0 = *reinterpret_cast<const float4*>(g_V + (size_t)s0 * HD + lane * 4);
        av.x = fmaf(v0.x, sc0, av.x); av.y = fmaf(v0.y, sc0, av.y);
        av.z = fmaf(v0.z, sc0, av.z); av.w = fmaf(v0.w, sc0, av.w);
        if ((lane & 3) == 0) z += sc0;
    }

    z = __shfl_sync(0xffffffffu, z, lane & ~3);
    const float inv = 1.f / z;

    float4 o;
    o.x = av.x * inv; o.y = av.y * inv; o.z = av.z * inv; o.w = av.w * inv;
    *reinterpret_cast<float4*>(out + (size_t)w * HD + lane * 4) = o;
}

// ---------------------------------------------------------------------------
extern "C" void kernel_launch(void* const* d_in, const int* in_sizes, int n_in,
                              void* d_out, int out_size)
{
    const float* h  = (const float*)d_in[0];
    const int* src  = (const int*)d_in[1];
    const int* dst  = (const int*)d_in[2];
    const float* Wq = (const float*)d_in[3];
    const float* Wk = (const float*)d_in[4];
    const float* Wv = (const float*)d_in[5];
    const float* bq = (const float*)d_in[6];
    const float* bk = (const float*)d_in[7];
    const float* bv = (const float*)d_in[8];
    float* out = (float*)d_out;

    const int N = in_sizes[0] / IN_DIM;
    const int E = in_sizes[1];

    // One-time setup on the uncaptured correctness call
    static cudaStream_t s2 = nullptr;
    static cudaEvent_t evFork = nullptr, evJoin = nullptr;
    static void* degptr = nullptr;
    if (s2 == nullptr) {
        cudaStreamCreateWithFlags(&s2, cudaStreamNonBlocking);
        cudaEventCreateWithFlags(&evFork, cudaEventDisableTiming);
        cudaEventCreateWithFlags(&evJoin, cudaEventDisableTiming);
        cudaFuncSetAttribute(qkv_kernel, cudaFuncAttributeMaxDynamicSharedMemorySize,
                             QKV_SMEM_BYTES);
        cudaGetSymbolAddress(&degptr, g_deg);
    }

    const int eb = (E + 255) / 256;

    // Fork: CSR build on s2, QKV GEMM on the main (capture) stream.
    cudaEventRecord(evFork, 0);
    cudaStreamWaitEvent(s2, evFork, 0);

    cudaMemsetAsync(degptr, 0, (size_t)N * sizeof(int), s2);
    hist_kernel<<<eb, 256, 0, s2>>>(dst, E);
    scan_kernel<<<1, 1024, 0, s2>>>(N);
    scatter_kernel<<<eb, 256, 0, s2>>>(src, dst, E);
    cudaEventRecord(evJoin, s2);

    dim3 gemm_grid((N + QN - 1) / QN, 3);
    qkv_kernel<<<gemm_grid, 256, QKV_SMEM_BYTES>>>(h, Wq, Wk, Wv, bq, bk, bv, N);

    // Join, then attention (warp per dst node)
    cudaStreamWaitEvent(0, evJoin, 0);
    attn_kernel<<<(N * 32 + 255) / 256, 256>>>(out, N);
}

// round 5
// speedup vs baseline: 1.2019x; 1.1938x over previous
#include <cuda_runtime.h>
#include <cuda_bf16.h>
#include <cstdint>

typedef unsigned long long ull;

// Problem constants (fixed by the dataset)
#define MAXN 50000
#define MAXE 800000
#define IN_DIM 128
#define NUM_HEADS 8
#define HEAD_DIM 16
#define HD 128              // NUM_HEADS*HEAD_DIM
#define TILE_N 64           // nodes per block tile in QKV GEMM
#define HT_STRIDE 68        // padded n-stride for transposed h tile

// ---- scratch (static device arrays; no allocation allowed) ----
__device__ float g_Q[(size_t)MAXN * HD];   // pre-scaled by 0.25
__device__ float g_K[(size_t)MAXN * HD];
__device__ float g_V[(size_t)MAXN * HD];
__device__ int   g_deg[MAXN];
__device__ int   g_off[MAXN];              // after scatter: g_off[d] = segment END of d
__device__ int   g_src_sorted[MAXE];

// ---------------------------------------------------------------------------
// Kernel 1: QKV projection, tiled SGEMM with packed f32x2 FMA.
// grid = (ceil(N/64), 3); blockIdx.y selects {Q,K,V}.
// Block tile: 64 nodes x 128 cols, 256 threads.
// Thread (cg=tid&31, ng=tid>>5) owns an 8-node x 4-col micro-tile as 16
// packed f32x2 accumulators (pairs over adjacent nodes -> h loads are
// naturally packed; W scalar broadcast into both halves via mov.b64).
// h tile transposed in smem (35 KB only -> 6 blocks/SM); W read via __ldg:
// all 8 warps hit the same 512B per k, L1-resident across the k loop.
// ---------------------------------------------------------------------------
__global__ __launch_bounds__(256) void qkv_kernel(
    const float* __restrict__ h,
    const float* __restrict__ Wq, const float* __restrict__ Wk, const float* __restrict__ Wv,
    const float* __restrict__ bq, const float* __restrict__ bk, const float* __restrict__ bv,
    int N)
{
    __shared__ alignas(16) float hT[IN_DIM][HT_STRIDE];

    const int m  = blockIdx.y;           // 0=Q, 1=K, 2=V
    const float* W = (m == 0) ? Wq : ((m == 1) ? Wk : Wv);
    const float* b = (m == 0) ? bq : ((m == 1) ? bk : bv);
    float* outbuf  = (m == 0) ? g_Q : ((m == 1) ? g_K : g_V);
    const float mul = (m == 0) ? 0.25f : 1.0f;

    const int n0  = blockIdx.x * TILE_N;
    const int tid = threadIdx.x;

    // Stage h tile transposed: hT[k][n] = h[n0+n][k] (coalesced reads)
    for (int idx = tid; idx < TILE_N * IN_DIM; idx += 256) {
        int n = idx >> 7;
        int k = idx & 127;
        float v = 0.f;
        if (n0 + n < N) v = h[(size_t)(n0 + n) * IN_DIM + k];
        hT[k][n] = v;
    }
    __syncthreads();

    const int cg = tid & 31;   // col group: cols [4*cg, 4*cg+4)
    const int ng = tid >> 5;   // node group: nodes [8*ng, 8*ng+8)
    const int col0 = cg * 4;

    const unsigned sbase = (unsigned)__cvta_generic_to_shared(&hT[0][0]);
    const unsigned hbase = sbase + (unsigned)(ng * 8) * 4u;   // + k*HT_STRIDE*4

    const float* Wp = W + col0;          // + k*HD

    ull acc[16];
#pragma unroll
    for (int i = 0; i < 16; i++) acc[i] = 0ull;

#pragma unroll 8
    for (int k = 0; k < IN_DIM; k++) {
        const unsigned ha = hbase + (unsigned)k * (HT_STRIDE * 4);

        ull h01, h23, h45, h67;
        asm volatile("ld.shared.v2.b64 {%0,%1}, [%2];"
                     : "=l"(h01), "=l"(h23) : "r"(ha));
        asm volatile("ld.shared.v2.b64 {%0,%1}, [%2];"
                     : "=l"(h45), "=l"(h67) : "r"(ha + 16u));

        const float4 w = __ldg(reinterpret_cast<const float4*>(Wp + (size_t)k * HD));

        ull wp0, wp1, wp2, wp3;
        asm("mov.b64 %0, {%1,%1};" : "=l"(wp0) : "f"(w.x));
        asm("mov.b64 %0, {%1,%1};" : "=l"(wp1) : "f"(w.y));
        asm("mov.b64 %0, {%1,%1};" : "=l"(wp2) : "f"(w.z));
        asm("mov.b64 %0, {%1,%1};" : "=l"(wp3) : "f"(w.w));

#define FMA2(a, hp, wp) asm("fma.rn.f32x2 %0, %1, %2, %0;" : "+l"(a) : "l"(hp), "l"(wp))
        FMA2(acc[ 0], h01, wp0); FMA2(acc[ 1], h01, wp1);
        FMA2(acc[ 2], h01, wp2); FMA2(acc[ 3], h01, wp3);
        FMA2(acc[ 4], h23, wp0); FMA2(acc[ 5], h23, wp1);
        FMA2(acc[ 6], h23, wp2); FMA2(acc[ 7], h23, wp3);
        FMA2(acc[ 8], h45, wp0); FMA2(acc[ 9], h45, wp1);
        FMA2(acc[10], h45, wp2); FMA2(acc[11], h45, wp3);
        FMA2(acc[12], h67, wp0); FMA2(acc[13], h67, wp1);
        FMA2(acc[14], h67, wp2); FMA2(acc[15], h67, wp3);
#undef FMA2
    }

    const float4 bj = __ldg(reinterpret_cast<const float4*>(b + col0));

    // acc[np*4 + c] holds nodes (8*ng + 2*np, +1) for column col0+c
#pragma unroll
    for (int np = 0; np < 4; np++) {
        float lo[4], hi[4];
#pragma unroll
        for (int c = 0; c < 4; c++) {
            unsigned l, hh;
            asm("mov.b64 {%0,%1}, %2;" : "=r"(l), "=r"(hh) : "l"(acc[np * 4 + c]));
            lo[c] = __uint_as_float(l);
            hi[c] = __uint_as_float(hh);
        }
        int nodeA = n0 + ng * 8 + 2 * np;
        int nodeB = nodeA + 1;
        if (nodeA < N) {
            float4 o;
            o.x = (lo[0] + bj.x) * mul; o.y = (lo[1] + bj.y) * mul;
            o.z = (lo[2] + bj.z) * mul; o.w = (lo[3] + bj.w) * mul;
            *reinterpret_cast<float4*>(&outbuf[(size_t)nodeA * HD + col0]) = o;
        }
        if (nodeB < N) {
            float4 o;
            o.x = (hi[0] + bj.x) * mul; o.y = (hi[1] + bj.y) * mul;
            o.z = (hi[2] + bj.z) * mul; o.w = (hi[3] + bj.w) * mul;
            *reinterpret_cast<float4*>(&outbuf[(size_t)nodeB * HD + col0]) = o;
        }
    }
}

// ---------------------------------------------------------------------------
// CSR build: hist -> single-block scan -> scatter (atomic bump on g_off)
// ---------------------------------------------------------------------------
__global__ void hist_kernel(const int* __restrict__ dst, int E)
{
    int i = blockIdx.x * blockDim.x + threadIdx.x;
    if (i < E) atomicAdd(&g_deg[dst[i]], 1);
}

__global__ __launch_bounds__(1024) void scan_kernel(int N)
{
    __shared__ int warp_sums[32];
    __shared__ int s_carry;
    const int t = threadIdx.x;
    const int lane = t & 31, wid = t >> 5;
    if (t == 0) s_carry = 0;
    __syncthreads();

    for (int base = 0; base < N; base += 1024) {
        int i = base + t;
        int x = (i < N) ? g_deg[i] : 0;
        int inc = x;
#pragma unroll
        for (int d = 1; d < 32; d <<= 1) {
            int v = __shfl_up_sync(0xffffffffu, inc, d);
            if (lane >= d) inc += v;
        }
        if (lane == 31) warp_sums[wid] = inc;
        __syncthreads();
        if (wid == 0) {
            int ws = warp_sums[lane];
#pragma unroll
            for (int d = 1; d < 32; d <<= 1) {
                int v = __shfl_up_sync(0xffffffffu, ws, d);
                if (lane >= d) ws += v;
            }
            warp_sums[lane] = ws;   // inclusive over warp totals
        }
        __syncthreads();
        int warp_off = (wid > 0) ? warp_sums[wid - 1] : 0;
        if (i < N) g_off[i] = s_carry + warp_off + inc - x;   // exclusive
        int block_total = warp_sums[31];
        __syncthreads();
        if (t == 0) s_carry += block_total;
        __syncthreads();
    }
}

__global__ void scatter_kernel(const int* __restrict__ src, const int* __restrict__ dst, int E)
{
    int i = blockIdx.x * blockDim.x + threadIdx.x;
    if (i < E) {
        int d = dst[i];
        int p = atomicAdd(&g_off[d], 1);    // post: g_off[d] = end of segment d
        g_src_sorted[p] = src[i];
    }
}

// ---------------------------------------------------------------------------
// Kernel 3: warp-per-dst attention, unroll-2.
// Lane l owns dims [4l,4l+4) => head l>>2.
// beg = (w==0) ? 0 : g_off[w-1], end = g_off[w].
// ---------------------------------------------------------------------------
__global__ void attn_kernel(float* __restrict__ out, int N)
{
    const int lane = threadIdx.x & 31;
    const int w = (blockIdx.x * blockDim.x + threadIdx.x) >> 5;
    if (w >= N) return;

    const int beg = (w == 0) ? 0 : __ldg(&g_off[w - 1]);
    const int end = __ldg(&g_off[w]);

    const float4 q = *reinterpret_cast<const float4*>(g_Q + (size_t)w * HD + lane * 4);

    float4 av = make_float4(0.f, 0.f, 0.f, 0.f);
    float z = 0.f;

    int e = beg;
    for (; e + 2 <= end; e += 2) {
        const int s0 = __ldg(&g_src_sorted[e]);
        const int s1 = __ldg(&g_src_sorted[e + 1]);

        const float4 k0 = *reinterpret_cast<const float4*>(g_K + (size_t)s0 * HD + lane * 4);
        const float4 k1 = *reinterpret_cast<const float4*>(g_K + (size_t)s1 * HD + lane * 4);
        const float4 v0 = *reinterpret_cast<const float4*>(g_V + (size_t)s0 * HD + lane * 4);
        const float4 v1 = *reinterpret_cast<const float4*>(g_V + (size_t)s1 * HD + lane * 4);

        float sc0 = q.x * k0.x + q.y * k0.y + q.z * k0.z + q.w * k0.w;
        float sc1 = q.x * k1.x + q.y * k1.y + q.z * k1.z + q.w * k1.w;
        sc0 += __shfl_xor_sync(0xffffffffu, sc0, 1);
        sc1 += __shfl_xor_sync(0xffffffffu, sc1, 1);
        sc0 += __shfl_xor_sync(0xffffffffu, sc0, 2);
        sc1 += __shfl_xor_sync(0xffffffffu, sc1, 2);
        sc0 = __expf(fminf(fmaxf(sc0, -5.f), 5.f));
        sc1 = __expf(fminf(fmaxf(sc1, -5.f), 5.f));

        av.x = fmaf(v0.x, sc0, av.x); av.y = fmaf(v0.y, sc0, av.y);
        av.z = fmaf(v0.z, sc0, av.z); av.w = fmaf(v0.w, sc0, av.w);
        av.x = fmaf(v1.x, sc1, av.x); av.y = fmaf(v1.y, sc1, av.y);
        av.z = fmaf(v1.z, sc1, av.z); av.w = fmaf(v1.w, sc1, av.w);
        if ((lane & 3) == 0) z += sc0 + sc1;
    }
    if (e < end) {
        const int s0 = __ldg(&g_src_sorted[e]);
        const float4 k0 = *reinterpret_cast<const float4*>(g_K + (size_t)s0 * HD + lane * 4);
        float sc0 = q.x * k0.x + q.y * k0.y + q.z * k0.z + q.w * k0.w;
        sc0 += __shfl_xor_sync(0xffffffffu, sc0, 1);
        sc0 += __shfl_xor_sync(0xffffffffu, sc0, 2);
        sc0 = __expf(fminf(fmaxf(sc0, -5.f), 5.f));
        const float4 v0 = *reinterpret_cast<const float4*>(g_V + (size_t)s0 * HD + lane * 4);
        av.x = fmaf(v0.x, sc0, av.x); av.y = fmaf(v0.y, sc0, av.y);
        av.z = fmaf(v0.z, sc0, av.z); av.w = fmaf(v0.w, sc0, av.w);
        if ((lane & 3) == 0) z += sc0;
    }

    z = __shfl_sync(0xffffffffu, z, lane & ~3);
    const float inv = 1.f / z;

    float4 o;
    o.x = av.x * inv; o.y = av.y * inv; o.z = av.z * inv; o.w = av.w * inv;
    *reinterpret_cast<float4*>(out + (size_t)w * HD + lane * 4) = o;
}

// ---------------------------------------------------------------------------
extern "C" void kernel_launch(void* const* d_in, const int* in_sizes, int n_in,
                              void* d_out, int out_size)
{
    const float* h  = (const float*)d_in[0];
    const int* src  = (const int*)d_in[1];
    const int* dst  = (const int*)d_in[2];
    const float* Wq = (const float*)d_in[3];
    const float* Wk = (const float*)d_in[4];
    const float* Wv = (const float*)d_in[5];
    const float* bq = (const float*)d_in[6];
    const float* bk = (const float*)d_in[7];
    const float* bv = (const float*)d_in[8];
    float* out = (float*)d_out;

    const int N = in_sizes[0] / IN_DIM;
    const int E = in_sizes[1];

    // One-time setup on the uncaptured correctness call
    static cudaStream_t s2 = nullptr;
    static cudaEvent_t evFork = nullptr, evJoin = nullptr;
    static void* degptr = nullptr;
    if (s2 == nullptr) {
        cudaStreamCreateWithFlags(&s2, cudaStreamNonBlocking);
        cudaEventCreateWithFlags(&evFork, cudaEventDisableTiming);
        cudaEventCreateWithFlags(&evJoin, cudaEventDisableTiming);
        cudaGetSymbolAddress(&degptr, g_deg);
    }

    const int eb = (E + 255) / 256;

    // Fork: CSR build on s2, QKV GEMM on the main (capture) stream.
    cudaEventRecord(evFork, 0);
    cudaStreamWaitEvent(s2, evFork, 0);

    cudaMemsetAsync(degptr, 0, (size_t)N * sizeof(int), s2);
    hist_kernel<<<eb, 256, 0, s2>>>(dst, E);
    scan_kernel<<<1, 1024, 0, s2>>>(N);
    scatter_kernel<<<eb, 256, 0, s2>>>(src, dst, E);
    cudaEventRecord(evJoin, s2);

    dim3 gemm_grid((N + TILE_N - 1) / TILE_N, 3);
    qkv_kernel<<<gemm_grid, 256>>>(h, Wq, Wk, Wv, bq, bk, bv, N);

    // Join, then attention (warp per dst node)
    cudaStreamWaitEvent(0, evJoin, 0);
    attn_kernel<<<(N * 32 + 255) / 256, 256>>>(out, N);
}

// round 7
// speedup vs baseline: 1.7003x; 1.4147x over previous
#include <cuda_runtime.h>
#include <cuda_bf16.h>
#include <cstdint>

// Problem constants
#define MAXN 50000
#define MAXE 800000
#define IN_DIM 128
#define HD 128
#define ASTRIDE 136               // bf16 elems per smem row (272B, conflict-free ldmatrix)
#define TILE_BYTES (128 * ASTRIDE * 2)          // 34816 B per split image
#define QKV_SMEM (4 * TILE_BYTES)               // Ahi,Alo,Bhi,Blo = 139264 B

// ---- scratch (static device arrays; no allocation allowed) ----
__device__ float g_Q[(size_t)MAXN * HD];   // pre-scaled by 0.25
__device__ float g_K[(size_t)MAXN * HD];
__device__ float g_V[(size_t)MAXN * HD];
__device__ int   g_deg[MAXN];
__device__ int   g_off[MAXN];              // after scatter: g_off[d] = segment END of d
__device__ int   g_src_sorted[MAXE];
// W^T hi/lo padded images: [matrix][split][n=128 rows][ASTRIDE k-cols]
__device__ __nv_bfloat16 g_Bimg[3][2][128 * ASTRIDE];

__device__ __forceinline__ uint32_t smem_u32(const void* p) {
    uint32_t a;
    asm("{ .reg .u64 t; cvta.to.shared.u64 t, %1; cvt.u32.u64 %0, t; }" : "=r"(a) : "l"(p));
    return a;
}

#define LDSM_X4(r0, r1, r2, r3, addr)                                            \
    asm volatile("ldmatrix.sync.aligned.m8n8.x4.shared.b16 {%0,%1,%2,%3}, [%4];" \
                 : "=r"(r0), "=r"(r1), "=r"(r2), "=r"(r3) : "r"(addr))

#define MMA16816(c, a0, a1, a2, a3, b0, b1)                                      \
    asm volatile("mma.sync.aligned.m16n8k16.row.col.f32.bf16.bf16.f32 "          \
                 "{%0,%1,%2,%3}, {%4,%5,%6,%7}, {%8,%9}, {%0,%1,%2,%3};"         \
                 : "+f"((c)[0]), "+f"((c)[1]), "+f"((c)[2]), "+f"((c)[3])        \
                 : "r"(a0), "r"(a1), "r"(a2), "r"(a3), "r"(b0), "r"(b1))

// ---------------------------------------------------------------------------
// Prepass: W^T hi/lo padded bf16 images. B[n][k] = W[k][n].
// ---------------------------------------------------------------------------
__global__ void wprep_kernel(const float* __restrict__ Wq,
                             const float* __restrict__ Wk,
                             const float* __restrict__ Wv)
{
    int idx = blockIdx.x * blockDim.x + threadIdx.x;
    if (idx >= 3 * 128 * 128) return;
    int m = idx >> 14, rem = idx & 16383, n = rem >> 7, k = rem & 127;
    const float* W = (m == 0) ? Wq : ((m == 1) ? Wk : Wv);
    float w = W[k * 128 + n];
    __nv_bfloat16 hi = __float2bfloat16(w);
    __nv_bfloat16 lo = __float2bfloat16(w - __bfloat162float(hi));
    g_Bimg[m][0][n * ASTRIDE + k] = hi;
    g_Bimg[m][1][n * ASTRIDE + k] = lo;
}

// ---------------------------------------------------------------------------
// Kernel 1: QKV projection via mma.sync bf16 split-GEMM.
// Block: 128 nodes x 128 cols, 256 threads (8 warps: 4 m-chunks x 2 n-chunks).
// Warp: 32 rows x 64 cols = 2 m-tiles x 8 n-tiles, fp32 accum.
// Products: Ahi*Bhi + Ahi*Blo + Alo*Bhi.
// ---------------------------------------------------------------------------
__global__ __launch_bounds__(256) void qkv_mma_kernel(
    const float* __restrict__ h,
    const float* __restrict__ bq, const float* __restrict__ bk, const float* __restrict__ bv,
    int N)
{
    extern __shared__ __nv_bfloat16 smem[];
    __nv_bfloat16* Ahi = smem;
    __nv_bfloat16* Alo = smem + 128 * ASTRIDE;
    __nv_bfloat16* Bhi = smem + 2 * 128 * ASTRIDE;
    __nv_bfloat16* Blo = smem + 3 * 128 * ASTRIDE;

    const int tid = threadIdx.x;
    const int lane = tid & 31, warp = tid >> 5;
    const int wm = warp & 3;       // m-chunk: rows [32*wm, 32*wm+32)
    const int wn = warp >> 2;      // n-chunk: cols [64*wn, 64*wn+64)
    const int node0 = blockIdx.x * 128;

    // ---- Stage A: fp32 -> bf16 hi/lo. Thread t: row t>>1, col-half t&1. ----
    {
        const int r = tid >> 1, cb = (tid & 1) * 64;
        const bool valid = (node0 + r) < N;
        const float* hp = h + (size_t)(node0 + r) * IN_DIM + cb;
        __nv_bfloat16* ah = Ahi + r * ASTRIDE + cb;
        __nv_bfloat16* al = Alo + r * ASTRIDE + cb;
#pragma unroll
        for (int i = 0; i < 64; i += 4) {
            float4 v = valid ? *reinterpret_cast<const float4*>(hp + i)
                             : make_float4(0.f, 0.f, 0.f, 0.f);
            __nv_bfloat162 h0 = __floats2bfloat162_rn(v.x, v.y);
            __nv_bfloat162 h1 = __floats2bfloat162_rn(v.z, v.w);
            __nv_bfloat162 l0 = __floats2bfloat162_rn(v.x - __bfloat162float(h0.x),
                                                      v.y - __bfloat162float(h0.y));
            __nv_bfloat162 l1 = __floats2bfloat162_rn(v.z - __bfloat162float(h1.x),
                                                      v.w - __bfloat162float(h1.y));
            *reinterpret_cast<__nv_bfloat162*>(ah + i)     = h0;
            *reinterpret_cast<__nv_bfloat162*>(ah + i + 2) = h1;
            *reinterpret_cast<__nv_bfloat162*>(al + i)     = l0;
            *reinterpret_cast<__nv_bfloat162*>(al + i + 2) = l1;
        }
    }

    const uint32_t uAhi = smem_u32(Ahi), uAlo = smem_u32(Alo);
    const uint32_t uBhi = smem_u32(Bhi), uBlo = smem_u32(Blo);

    // ldmatrix lane address components
    // A: row = wm*32 + mt*16 + (lane&15); byte += (lane>>4)*16 + kk*32
    const uint32_t aRow = (uint32_t)(wm * 32 + (lane & 15)) * 272u + (uint32_t)(lane >> 4) * 16u;
    // B: n-row = wn*64 + p*16 + ((lane>>4)&1)*8 + (lane&7); byte += ((lane>>3)&1)*16 + kk*32
    const uint32_t bRow = (uint32_t)(wn * 64 + ((lane >> 4) & 1) * 8 + (lane & 7)) * 272u
                        + (uint32_t)((lane >> 3) & 1) * 16u;

    const float* biases[3] = {bq, bk, bv};
    float* outs[3] = {g_Q, g_K, g_V};

    for (int m = 0; m < 3; m++) {
        // ---- Stage B (hi+lo images of matrix m), after prior consumers done ----
        __syncthreads();
        {
            const float4* sh = reinterpret_cast<const float4*>(g_Bimg[m][0]);
            const float4* sl = reinterpret_cast<const float4*>(g_Bimg[m][1]);
            float4* dh = reinterpret_cast<float4*>(Bhi);
            float4* dl = reinterpret_cast<float4*>(Blo);
            for (int i = tid; i < TILE_BYTES / 16; i += 256) { dh[i] = sh[i]; dl[i] = sl[i]; }
        }
        __syncthreads();

        float acc[2][8][4];
#pragma unroll
        for (int mt = 0; mt < 2; mt++)
#pragma unroll
            for (int nt = 0; nt < 8; nt++)
#pragma unroll
                for (int c = 0; c < 4; c++) acc[mt][nt][c] = 0.f;

#pragma unroll
        for (int kk = 0; kk < 8; kk++) {
            const uint32_t kO = (uint32_t)kk * 32u;

            uint32_t ah[2][4], al[2][4];
#pragma unroll
            for (int mt = 0; mt < 2; mt++) {
                const uint32_t ro = aRow + (uint32_t)(mt * 16) * 272u + kO;
                LDSM_X4(ah[mt][0], ah[mt][1], ah[mt][2], ah[mt][3], uAhi + ro);
                LDSM_X4(al[mt][0], al[mt][1], al[mt][2], al[mt][3], uAlo + ro);
            }

            uint32_t bh[8][2], bl[8][2];
#pragma unroll
            for (int p = 0; p < 4; p++) {
                const uint32_t ro = bRow + (uint32_t)(p * 16) * 272u + kO;
                LDSM_X4(bh[2 * p][0], bh[2 * p][1], bh[2 * p + 1][0], bh[2 * p + 1][1], uBhi + ro);
                LDSM_X4(bl[2 * p][0], bl[2 * p][1], bl[2 * p + 1][0], bl[2 * p + 1][1], uBlo + ro);
            }

#pragma unroll
            for (int mt = 0; mt < 2; mt++)
#pragma unroll
                for (int nt = 0; nt < 8; nt++) {
                    MMA16816(acc[mt][nt], ah[mt][0], ah[mt][1], ah[mt][2], ah[mt][3],
                             bh[nt][0], bh[nt][1]);
                    MMA16816(acc[mt][nt], ah[mt][0], ah[mt][1], ah[mt][2], ah[mt][3],
                             bl[nt][0], bl[nt][1]);
                    MMA16816(acc[mt][nt], al[mt][0], al[mt][1], al[mt][2], al[mt][3],
                             bh[nt][0], bh[nt][1]);
                }
        }

        // ---- Epilogue: c0,c1 -> (row, col..col+1); c2,c3 -> (row+8) ----
        const float mul = (m == 0) ? 0.25f : 1.0f;
        const float* bb = biases[m];
        float* ob = outs[m];
#pragma unroll
        for (int mt = 0; mt < 2; mt++) {
            const int r0 = node0 + wm * 32 + mt * 16 + (lane >> 2);
#pragma unroll
            for (int nt = 0; nt < 8; nt++) {
                const int col = wn * 64 + nt * 8 + (lane & 3) * 2;
                const float b0 = __ldg(bb + col), b1 = __ldg(bb + col + 1);
                if (r0 < N) {
                    float2 o = make_float2((acc[mt][nt][0] + b0) * mul,
                                           (acc[mt][nt][1] + b1) * mul);
                    *reinterpret_cast<float2*>(ob + (size_t)r0 * HD + col) = o;
                }
                if (r0 + 8 < N) {
                    float2 o = make_float2((acc[mt][nt][2] + b0) * mul,
                                           (acc[mt][nt][3] + b1) * mul);
                    *reinterpret_cast<float2*>(ob + (size_t)(r0 + 8) * HD + col) = o;
                }
            }
        }
    }
}

// ---------------------------------------------------------------------------
// CSR build: hist -> single-block scan -> scatter (atomic bump on g_off)
// ---------------------------------------------------------------------------
__global__ void hist_kernel(const int* __restrict__ dst, int E)
{
    int i = blockIdx.x * blockDim.x + threadIdx.x;
    if (i < E) atomicAdd(&g_deg[dst[i]], 1);
}

__global__ __launch_bounds__(1024) void scan_kernel(int N)
{
    __shared__ int warp_sums[32];
    __shared__ int s_carry;
    const int t = threadIdx.x;
    const int lane = t & 31, wid = t >> 5;
    if (t == 0) s_carry = 0;
    __syncthreads();

    for (int base = 0; base < N; base += 1024) {
        int i = base + t;
        int x = (i < N) ? g_deg[i] : 0;
        int inc = x;
#pragma unroll
        for (int d = 1; d < 32; d <<= 1) {
            int v = __shfl_up_sync(0xffffffffu, inc, d);
            if (lane >= d) inc += v;
        }
        if (lane == 31) warp_sums[wid] = inc;
        __syncthreads();
        if (wid == 0) {
            int ws = warp_sums[lane];
#pragma unroll
            for (int d = 1; d < 32; d <<= 1) {
                int v = __shfl_up_sync(0xffffffffu, ws, d);
                if (lane >= d) ws += v;
            }
            warp_sums[lane] = ws;
        }
        __syncthreads();
        int warp_off = (wid > 0) ? warp_sums[wid - 1] : 0;
        if (i < N) g_off[i] = s_carry + warp_off + inc - x;
        int block_total = warp_sums[31];
        __syncthreads();
        if (t == 0) s_carry += block_total;
        __syncthreads();
    }
}

__global__ void scatter_kernel(const int* __restrict__ src, const int* __restrict__ dst, int E)
{
    int i = blockIdx.x * blockDim.x + threadIdx.x;
    if (i < E) {
        int d = dst[i];
        int p = atomicAdd(&g_off[d], 1);
        g_src_sorted[p] = src[i];
    }
}

// ---------------------------------------------------------------------------
// Kernel 3: warp-per-dst attention, unroll-2. Lane l owns dims [4l,4l+4).
// ---------------------------------------------------------------------------
__global__ void attn_kernel(float* __restrict__ out, int N)
{
    const int lane = threadIdx.x & 31;
    const int w = (blockIdx.x * blockDim.x + threadIdx.x) >> 5;
    if (w >= N) return;

    const int beg = (w == 0) ? 0 : __ldg(&g_off[w - 1]);
    const int end = __ldg(&g_off[w]);

    const float4 q = *reinterpret_cast<const float4*>(g_Q + (size_t)w * HD + lane * 4);

    float4 av = make_float4(0.f, 0.f, 0.f, 0.f);
    float z = 0.f;

    int e = beg;
    for (; e + 2 <= end; e += 2) {
        const int s0 = __ldg(&g_src_sorted[e]);
        const int s1 = __ldg(&g_src_sorted[e + 1]);

        const float4 k0 = *reinterpret_cast<const float4*>(g_K + (size_t)s0 * HD + lane * 4);
        const float4 k1 = *reinterpret_cast<const float4*>(g_K + (size_t)s1 * HD + lane * 4);
        const float4 v0 = *reinterpret_cast<const float4*>(g_V + (size_t)s0 * HD + lane * 4);
        const float4 v1 = *reinterpret_cast<const float4*>(g_V + (size_t)s1 * HD + lane * 4);

        float sc0 = q.x * k0.x + q.y * k0.y + q.z * k0.z + q.w * k0.w;
        float sc1 = q.x * k1.x + q.y * k1.y + q.z * k1.z + q.w * k1.w;
        sc0 += __shfl_xor_sync(0xffffffffu, sc0, 1);
        sc1 += __shfl_xor_sync(0xffffffffu, sc1, 1);
        sc0 += __shfl_xor_sync(0xffffffffu, sc0, 2);
        sc1 += __shfl_xor_sync(0xffffffffu, sc1, 2);
        sc0 = __expf(fminf(fmaxf(sc0, -5.f), 5.f));
        sc1 = __expf(fminf(fmaxf(sc1, -5.f), 5.f));

        av.x = fmaf(v0.x, sc0, av.x); av.y = fmaf(v0.y, sc0, av.y);
        av.z = fmaf(v0.z, sc0, av.z); av.w = fmaf(v0.w, sc0, av.w);
        av.x = fmaf(v1.x, sc1, av.x); av.y = fmaf(v1.y, sc1, av.y);
        av.z = fmaf(v1.z, sc1, av.z); av.w = fmaf(v1.w, sc1, av.w);
        if ((lane & 3) == 0) z += sc0 + sc1;
    }
    if (e < end) {
        const int s0 = __ldg(&g_src_sorted[e]);
        const float4 k0 = *reinterpret_cast<const float4*>(g_K + (size_t)s0 * HD + lane * 4);
        float sc0 = q.x * k0.x + q.y * k0.y + q.z * k0.z + q.w * k0.w;
        sc0 += __shfl_xor_sync(0xffffffffu, sc0, 1);
        sc0 += __shfl_xor_sync(0xffffffffu, sc0, 2);
        sc0 = __expf(fminf(fmaxf(sc0, -5.f), 5.f));
        const float4 v0 = *reinterpret_cast<const float4*>(g_V + (size_t)s0 * HD + lane * 4);
        av.x = fmaf(v0.x, sc0, av.x); av.y = fmaf(v0.y, sc0, av.y);
        av.z = fmaf(v0.z, sc0, av.z); av.w = fmaf(v0.w, sc0, av.w);
        if ((lane & 3) == 0) z += sc0;
    }

    z = __shfl_sync(0xffffffffu, z, lane & ~3);
    const float inv = 1.f / z;

    float4 o;
    o.x = av.x * inv; o.y = av.y * inv; o.z = av.z * inv; o.w = av.w * inv;
    *reinterpret_cast<float4*>(out + (size_t)w * HD + lane * 4) = o;
}

// ---------------------------------------------------------------------------
extern "C" void kernel_launch(void* const* d_in, const int* in_sizes, int n_in,
                              void* d_out, int out_size)
{
    const float* h  = (const float*)d_in[0];
    const int* src  = (const int*)d_in[1];
    const int* dst  = (const int*)d_in[2];
    const float* Wq = (const float*)d_in[3];
    const float* Wk = (const float*)d_in[4];
    const float* Wv = (const float*)d_in[5];
    const float* bq = (const float*)d_in[6];
    const float* bk = (const float*)d_in[7];
    const float* bv = (const float*)d_in[8];
    float* out = (float*)d_out;

    const int N = in_sizes[0] / IN_DIM;
    const int E = in_sizes[1];

    // One-time setup on the uncaptured correctness call
    static cudaStream_t s2 = nullptr;
    static cudaEvent_t evFork = nullptr, evJoin = nullptr;
    static void* degptr = nullptr;
    if (s2 == nullptr) {
        cudaStreamCreateWithFlags(&s2, cudaStreamNonBlocking);
        cudaEventCreateWithFlags(&evFork, cudaEventDisableTiming);
        cudaEventCreateWithFlags(&evJoin, cudaEventDisableTiming);
        cudaGetSymbolAddress(&degptr, g_deg);
        cudaFuncSetAttribute(qkv_mma_kernel, cudaFuncAttributeMaxDynamicSharedMemorySize,
                             QKV_SMEM);
    }

    const int eb = (E + 255) / 256;

    // Fork: CSR build on s2; W prepass + tensor GEMM on the main (capture) stream.
    cudaEventRecord(evFork, 0);
    cudaStreamWaitEvent(s2, evFork, 0);

    cudaMemsetAsync(degptr, 0, (size_t)N * sizeof(int), s2);
    hist_kernel<<<eb, 256, 0, s2>>>(dst, E);
    scan_kernel<<<1, 1024, 0, s2>>>(N);
    scatter_kernel<<<eb, 256, 0, s2>>>(src, dst, E);
    cudaEventRecord(evJoin, s2);

    wprep_kernel<<<(3 * 128 * 128 + 255) / 256, 256>>>(Wq, Wk, Wv);
    qkv_mma_kernel<<<(N + 127) / 128, 256, QKV_SMEM>>>(h, bq, bk, bv, N);

    // Join, then attention (warp per dst node)
    cudaStreamWaitEvent(0, evJoin, 0);
    attn_kernel<<<(N * 32 + 255) / 256, 256>>>(out, N);
}

// round 8
// speedup vs baseline: 1.7967x; 1.0567x over previous
#include <cuda_runtime.h>
#include <cuda_bf16.h>
#include <cuda_fp16.h>
#include <cstdint>

// Problem constants
#define MAXN 50000
#define MAXE 800000
#define IN_DIM 128
#define HD 128
#define ASTRIDE 136               // bf16 elems per smem row (272B, conflict-free ldmatrix)
#define TILE_BYTES (128 * ASTRIDE * 2)          // 34816 B per split image
#define QKV_SMEM (4 * TILE_BYTES)               // Ahi,Alo,Bhi,Blo = 139264 B

// ---- scratch (static device arrays; no allocation allowed) ----
__device__ float  g_Q[(size_t)MAXN * HD];    // pre-scaled by 0.25, fp32
__device__ __half g_Kh[(size_t)MAXN * HD];   // fp16
__device__ __half g_Vh[(size_t)MAXN * HD];   // fp16
__device__ int    g_deg[MAXN];
__device__ int    g_off[MAXN];               // after scatter: g_off[d] = segment END of d
__device__ int    g_src_sorted[MAXE];
// W^T hi/lo padded images: [matrix][split][n=128 rows][ASTRIDE k-cols]
__device__ __nv_bfloat16 g_Bimg[3][2][128 * ASTRIDE];

__device__ __forceinline__ uint32_t smem_u32(const void* p) {
    uint32_t a;
    asm("{ .reg .u64 t; cvta.to.shared.u64 t, %1; cvt.u32.u64 %0, t; }" : "=r"(a) : "l"(p));
    return a;
}

#define LDSM_X4(r0, r1, r2, r3, addr)                                            \
    asm volatile("ldmatrix.sync.aligned.m8n8.x4.shared.b16 {%0,%1,%2,%3}, [%4];" \
                 : "=r"(r0), "=r"(r1), "=r"(r2), "=r"(r3) : "r"(addr))

#define MMA16816(c, a0, a1, a2, a3, b0, b1)                                      \
    asm volatile("mma.sync.aligned.m16n8k16.row.col.f32.bf16.bf16.f32 "          \
                 "{%0,%1,%2,%3}, {%4,%5,%6,%7}, {%8,%9}, {%0,%1,%2,%3};"         \
                 : "+f"((c)[0]), "+f"((c)[1]), "+f"((c)[2]), "+f"((c)[3])        \
                 : "r"(a0), "r"(a1), "r"(a2), "r"(a3), "r"(b0), "r"(b1))

// ---------------------------------------------------------------------------
// Prepass: W^T hi/lo padded bf16 images. B[n][k] = W[k][n].
// ---------------------------------------------------------------------------
__global__ void wprep_kernel(const float* __restrict__ Wq,
                             const float* __restrict__ Wk,
                             const float* __restrict__ Wv)
{
    int idx = blockIdx.x * blockDim.x + threadIdx.x;
    if (idx >= 3 * 128 * 128) return;
    int m = idx >> 14, rem = idx & 16383, n = rem >> 7, k = rem & 127;
    const float* W = (m == 0) ? Wq : ((m == 1) ? Wk : Wv);
    float w = W[k * 128 + n];
    __nv_bfloat16 hi = __float2bfloat16(w);
    __nv_bfloat16 lo = __float2bfloat16(w - __bfloat162float(hi));
    g_Bimg[m][0][n * ASTRIDE + k] = hi;
    g_Bimg[m][1][n * ASTRIDE + k] = lo;
}

// ---------------------------------------------------------------------------
// Kernel 1: QKV projection via mma.sync bf16 split-GEMM.
// Block: 128 nodes x 128 cols, 256 threads (8 warps: 4 m-chunks x 2 n-chunks).
// Warp: 32 rows x 64 cols = 2 m-tiles x 8 n-tiles, fp32 accum.
// Products: Ahi*Bhi + Ahi*Blo + Alo*Bhi.
// Epilogue: m=0 -> g_Q fp32 (pre-scaled 0.25); m=1/2 -> g_Kh/g_Vh fp16.
// ---------------------------------------------------------------------------
__global__ __launch_bounds__(256) void qkv_mma_kernel(
    const float* __restrict__ h,
    const float* __restrict__ bq, const float* __restrict__ bk, const float* __restrict__ bv,
    int N)
{
    extern __shared__ __nv_bfloat16 smem[];
    __nv_bfloat16* Ahi = smem;
    __nv_bfloat16* Alo = smem + 128 * ASTRIDE;
    __nv_bfloat16* Bhi = smem + 2 * 128 * ASTRIDE;
    __nv_bfloat16* Blo = smem + 3 * 128 * ASTRIDE;

    const int tid = threadIdx.x;
    const int lane = tid & 31, warp = tid >> 5;
    const int wm = warp & 3;       // m-chunk: rows [32*wm, 32*wm+32)
    const int wn = warp >> 2;      // n-chunk: cols [64*wn, 64*wn+64)
    const int node0 = blockIdx.x * 128;

    // ---- Stage A: fp32 -> bf16 hi/lo. Thread t: row t>>1, col-half t&1. ----
    {
        const int r = tid >> 1, cb = (tid & 1) * 64;
        const bool valid = (node0 + r) < N;
        const float* hp = h + (size_t)(node0 + r) * IN_DIM + cb;
        __nv_bfloat16* ah = Ahi + r * ASTRIDE + cb;
        __nv_bfloat16* al = Alo + r * ASTRIDE + cb;
#pragma unroll
        for (int i = 0; i < 64; i += 4) {
            float4 v = valid ? *reinterpret_cast<const float4*>(hp + i)
                             : make_float4(0.f, 0.f, 0.f, 0.f);
            __nv_bfloat162 h0 = __floats2bfloat162_rn(v.x, v.y);
            __nv_bfloat162 h1 = __floats2bfloat162_rn(v.z, v.w);
            __nv_bfloat162 l0 = __floats2bfloat162_rn(v.x - __bfloat162float(h0.x),
                                                      v.y - __bfloat162float(h0.y));
            __nv_bfloat162 l1 = __floats2bfloat162_rn(v.z - __bfloat162float(h1.x),
                                                      v.w - __bfloat162float(h1.y));
            *reinterpret_cast<__nv_bfloat162*>(ah + i)     = h0;
            *reinterpret_cast<__nv_bfloat162*>(ah + i + 2) = h1;
            *reinterpret_cast<__nv_bfloat162*>(al + i)     = l0;
            *reinterpret_cast<__nv_bfloat162*>(al + i + 2) = l1;
        }
    }

    const uint32_t uAhi = smem_u32(Ahi), uAlo = smem_u32(Alo);
    const uint32_t uBhi = smem_u32(Bhi), uBlo = smem_u32(Blo);

    // A: row = wm*32 + mt*16 + (lane&15); byte += (lane>>4)*16 + kk*32
    const uint32_t aRow = (uint32_t)(wm * 32 + (lane & 15)) * 272u + (uint32_t)(lane >> 4) * 16u;
    // B: n-row = wn*64 + p*16 + ((lane>>4)&1)*8 + (lane&7); byte += ((lane>>3)&1)*16 + kk*32
    const uint32_t bRow = (uint32_t)(wn * 64 + ((lane >> 4) & 1) * 8 + (lane & 7)) * 272u
                        + (uint32_t)((lane >> 3) & 1) * 16u;

    const float* biases[3] = {bq, bk, bv};

    for (int m = 0; m < 3; m++) {
        // ---- Stage B (hi+lo images of matrix m) ----
        __syncthreads();
        {
            const float4* sh = reinterpret_cast<const float4*>(g_Bimg[m][0]);
            const float4* sl = reinterpret_cast<const float4*>(g_Bimg[m][1]);
            float4* dh = reinterpret_cast<float4*>(Bhi);
            float4* dl = reinterpret_cast<float4*>(Blo);
            for (int i = tid; i < TILE_BYTES / 16; i += 256) { dh[i] = sh[i]; dl[i] = sl[i]; }
        }
        __syncthreads();

        float acc[2][8][4];
#pragma unroll
        for (int mt = 0; mt < 2; mt++)
#pragma unroll
            for (int nt = 0; nt < 8; nt++)
#pragma unroll
                for (int c = 0; c < 4; c++) acc[mt][nt][c] = 0.f;

#pragma unroll
        for (int kk = 0; kk < 8; kk++) {
            const uint32_t kO = (uint32_t)kk * 32u;

            uint32_t ah[2][4], al[2][4];
#pragma unroll
            for (int mt = 0; mt < 2; mt++) {
                const uint32_t ro = aRow + (uint32_t)(mt * 16) * 272u + kO;
                LDSM_X4(ah[mt][0], ah[mt][1], ah[mt][2], ah[mt][3], uAhi + ro);
                LDSM_X4(al[mt][0], al[mt][1], al[mt][2], al[mt][3], uAlo + ro);
            }

            uint32_t bh[8][2], bl[8][2];
#pragma unroll
            for (int p = 0; p < 4; p++) {
                const uint32_t ro = bRow + (uint32_t)(p * 16) * 272u + kO;
                LDSM_X4(bh[2 * p][0], bh[2 * p][1], bh[2 * p + 1][0], bh[2 * p + 1][1], uBhi + ro);
                LDSM_X4(bl[2 * p][0], bl[2 * p][1], bl[2 * p + 1][0], bl[2 * p + 1][1], uBlo + ro);
            }

#pragma unroll
            for (int mt = 0; mt < 2; mt++)
#pragma unroll
                for (int nt = 0; nt < 8; nt++) {
                    MMA16816(acc[mt][nt], ah[mt][0], ah[mt][1], ah[mt][2], ah[mt][3],
                             bh[nt][0], bh[nt][1]);
                    MMA16816(acc[mt][nt], ah[mt][0], ah[mt][1], ah[mt][2], ah[mt][3],
                             bl[nt][0], bl[nt][1]);
                    MMA16816(acc[mt][nt], al[mt][0], al[mt][1], al[mt][2], al[mt][3],
                             bh[nt][0], bh[nt][1]);
                }
        }

        // ---- Epilogue ----
        const float* bb = biases[m];
#pragma unroll
        for (int mt = 0; mt < 2; mt++) {
            const int r0 = node0 + wm * 32 + mt * 16 + (lane >> 2);
#pragma unroll
            for (int nt = 0; nt < 8; nt++) {
                const int col = wn * 64 + nt * 8 + (lane & 3) * 2;
                const float b0 = __ldg(bb + col), b1 = __ldg(bb + col + 1);
                if (m == 0) {
                    if (r0 < N) {
                        float2 o = make_float2((acc[mt][nt][0] + b0) * 0.25f,
                                               (acc[mt][nt][1] + b1) * 0.25f);
                        *reinterpret_cast<float2*>(g_Q + (size_t)r0 * HD + col) = o;
                    }
                    if (r0 + 8 < N) {
                        float2 o = make_float2((acc[mt][nt][2] + b0) * 0.25f,
                                               (acc[mt][nt][3] + b1) * 0.25f);
                        *reinterpret_cast<float2*>(g_Q + (size_t)(r0 + 8) * HD + col) = o;
                    }
                } else {
                    __half* dstp = (m == 1) ? g_Kh : g_Vh;
                    if (r0 < N) {
                        __half2 o = __floats2half2_rn(acc[mt][nt][0] + b0,
                                                      acc[mt][nt][1] + b1);
                        *reinterpret_cast<__half2*>(dstp + (size_t)r0 * HD + col) = o;
                    }
                    if (r0 + 8 < N) {
                        __half2 o = __floats2half2_rn(acc[mt][nt][2] + b0,
                                                      acc[mt][nt][3] + b1);
                        *reinterpret_cast<__half2*>(dstp + (size_t)(r0 + 8) * HD + col) = o;
                    }
                }
            }
        }
    }
}

// ---------------------------------------------------------------------------
// CSR build: hist -> single-block scan -> scatter (atomic bump on g_off)
// ---------------------------------------------------------------------------
__global__ void hist_kernel(const int* __restrict__ dst, int E)
{
    int i = blockIdx.x * blockDim.x + threadIdx.x;
    if (i < E) atomicAdd(&g_deg[dst[i]], 1);
}

__global__ __launch_bounds__(1024) void scan_kernel(int N)
{
    __shared__ int warp_sums[32];
    __shared__ int s_carry;
    const int t = threadIdx.x;
    const int lane = t & 31, wid = t >> 5;
    if (t == 0) s_carry = 0;
    __syncthreads();

    for (int base = 0; base < N; base += 1024) {
        int i = base + t;
        int x = (i < N) ? g_deg[i] : 0;
        int inc = x;
#pragma unroll
        for (int d = 1; d < 32; d <<= 1) {
            int v = __shfl_up_sync(0xffffffffu, inc, d);
            if (lane >= d) inc += v;
        }
        if (lane == 31) warp_sums[wid] = inc;
        __syncthreads();
        if (wid == 0) {
            int ws = warp_sums[lane];
#pragma unroll
            for (int d = 1; d < 32; d <<= 1) {
                int v = __shfl_up_sync(0xffffffffu, ws, d);
                if (lane >= d) ws += v;
            }
            warp_sums[lane] = ws;
        }
        __syncthreads();
        int warp_off = (wid > 0) ? warp_sums[wid - 1] : 0;
        if (i < N) g_off[i] = s_carry + warp_off + inc - x;
        int block_total = warp_sums[31];
        __syncthreads();
        if (t == 0) s_carry += block_total;
        __syncthreads();
    }
}

__global__ void scatter_kernel(const int* __restrict__ src, const int* __restrict__ dst, int E)
{
    int i = blockIdx.x * blockDim.x + threadIdx.x;
    if (i < E) {
        int d = dst[i];
        int p = atomicAdd(&g_off[d], 1);
        g_src_sorted[p] = src[i];
    }
}

// ---------------------------------------------------------------------------
// Kernel 3: warp-per-dst attention over fp16 K/V, unroll-2.
// Lane l owns dims [4l,4l+4) => head l>>2. Q fp32.
// ---------------------------------------------------------------------------
struct Half4 { __half2 a, b; };

__device__ __forceinline__ float4 h4_to_f4(Half4 x) {
    float2 lo = __half22float2(x.a), hi = __half22float2(x.b);
    return make_float4(lo.x, lo.y, hi.x, hi.y);
}

__global__ void attn_kernel(float* __restrict__ out, int N)
{
    const int lane = threadIdx.x & 31;
    const int w = (blockIdx.x * blockDim.x + threadIdx.x) >> 5;
    if (w >= N) return;

    const int beg = (w == 0) ? 0 : __ldg(&g_off[w - 1]);
    const int end = __ldg(&g_off[w]);

    const float4 q = *reinterpret_cast<const float4*>(g_Q + (size_t)w * HD + lane * 4);

    float4 av = make_float4(0.f, 0.f, 0.f, 0.f);
    float z = 0.f;

    int e = beg;
    for (; e + 2 <= end; e += 2) {
        const int s0 = __ldg(&g_src_sorted[e]);
        const int s1 = __ldg(&g_src_sorted[e + 1]);

        const Half4 K0 = *reinterpret_cast<const Half4*>(g_Kh + (size_t)s0 * HD + lane * 4);
        const Half4 K1 = *reinterpret_cast<const Half4*>(g_Kh + (size_t)s1 * HD + lane * 4);
        const Half4 V0 = *reinterpret_cast<const Half4*>(g_Vh + (size_t)s0 * HD + lane * 4);
        const Half4 V1 = *reinterpret_cast<const Half4*>(g_Vh + (size_t)s1 * HD + lane * 4);

        const float4 k0 = h4_to_f4(K0), k1 = h4_to_f4(K1);
        float sc0 = q.x * k0.x + q.y * k0.y + q.z * k0.z + q.w * k0.w;
        float sc1 = q.x * k1.x + q.y * k1.y + q.z * k1.z + q.w * k1.w;
        sc0 += __shfl_xor_sync(0xffffffffu, sc0, 1);
        sc1 += __shfl_xor_sync(0xffffffffu, sc1, 1);
        sc0 += __shfl_xor_sync(0xffffffffu, sc0, 2);
        sc1 += __shfl_xor_sync(0xffffffffu, sc1, 2);
        sc0 = __expf(fminf(fmaxf(sc0, -5.f), 5.f));
        sc1 = __expf(fminf(fmaxf(sc1, -5.f), 5.f));

        const float4 v0 = h4_to_f4(V0), v1 = h4_to_f4(V1);
        av.x = fmaf(v0.x, sc0, av.x); av.y = fmaf(v0.y, sc0, av.y);
        av.z = fmaf(v0.z, sc0, av.z); av.w = fmaf(v0.w, sc0, av.w);
        av.x = fmaf(v1.x, sc1, av.x); av.y = fmaf(v1.y, sc1, av.y);
        av.z = fmaf(v1.z, sc1, av.z); av.w = fmaf(v1.w, sc1, av.w);
        if ((lane & 3) == 0) z += sc0 + sc1;
    }
    if (e < end) {
        const int s0 = __ldg(&g_src_sorted[e]);
        const Half4 K0 = *reinterpret_cast<const Half4*>(g_Kh + (size_t)s0 * HD + lane * 4);
        const float4 k0 = h4_to_f4(K0);
        float sc0 = q.x * k0.x + q.y * k0.y + q.z * k0.z + q.w * k0.w;
        sc0 += __shfl_xor_sync(0xffffffffu, sc0, 1);
        sc0 += __shfl_xor_sync(0xffffffffu, sc0, 2);
        sc0 = __expf(fminf(fmaxf(sc0, -5.f), 5.f));
        const Half4 V0 = *reinterpret_cast<const Half4*>(g_Vh + (size_t)s0 * HD + lane * 4);
        const float4 v0 = h4_to_f4(V0);
        av.x = fmaf(v0.x, sc0, av.x); av.y = fmaf(v0.y, sc0, av.y);
        av.z = fmaf(v0.z, sc0, av.z); av.w = fmaf(v0.w, sc0, av.w);
        if ((lane & 3) == 0) z += sc0;
    }

    z = __shfl_sync(0xffffffffu, z, lane & ~3);
    const float inv = 1.f / z;

    float4 o;
    o.x = av.x * inv; o.y = av.y * inv; o.z = av.z * inv; o.w = av.w * inv;
    *reinterpret_cast<float4*>(out + (size_t)w * HD + lane * 4) = o;
}

// ---------------------------------------------------------------------------
extern "C" void kernel_launch(void* const* d_in, const int* in_sizes, int n_in,
                              void* d_out, int out_size)
{
    const float* h  = (const float*)d_in[0];
    const int* src  = (const int*)d_in[1];
    const int* dst  = (const int*)d_in[2];
    const float* Wq = (const float*)d_in[3];
    const float* Wk = (const float*)d_in[4];
    const float* Wv = (const float*)d_in[5];
    const float* bq = (const float*)d_in[6];
    const float* bk = (const float*)d_in[7];
    const float* bv = (const float*)d_in[8];
    float* out = (float*)d_out;

    const int N = in_sizes[0] / IN_DIM;
    const int E = in_sizes[1];

    // One-time setup on the uncaptured correctness call
    static cudaStream_t s2 = nullptr;
    static cudaEvent_t evFork = nullptr, evJoin = nullptr;
    static void* degptr = nullptr;
    if (s2 == nullptr) {
        cudaStreamCreateWithFlags(&s2, cudaStreamNonBlocking);
        cudaEventCreateWithFlags(&evFork, cudaEventDisableTiming);
        cudaEventCreateWithFlags(&evJoin, cudaEventDisableTiming);
        cudaGetSymbolAddress(&degptr, g_deg);
        cudaFuncSetAttribute(qkv_mma_kernel, cudaFuncAttributeMaxDynamicSharedMemorySize,
                             QKV_SMEM);
    }

    const int eb = (E + 255) / 256;

    // Fork: CSR build on s2; W prepass + tensor GEMM on the main (capture) stream.
    cudaEventRecord(evFork, 0);
    cudaStreamWaitEvent(s2, evFork, 0);

    cudaMemsetAsync(degptr, 0, (size_t)N * sizeof(int), s2);
    hist_kernel<<<eb, 256, 0, s2>>>(dst, E);
    scan_kernel<<<1, 1024, 0, s2>>>(N);
    scatter_kernel<<<eb, 256, 0, s2>>>(src, dst, E);
    cudaEventRecord(evJoin, s2);

    wprep_kernel<<<(3 * 128 * 128 + 255) / 256, 256>>>(Wq, Wk, Wv);
    qkv_mma_kernel<<<(N + 127) / 128, 256, QKV_SMEM>>>(h, bq, bk, bv, N);

    // Join, then attention (warp per dst node)
    cudaStreamWaitEvent(0, evJoin, 0);
    attn_kernel<<<(N * 32 + 255) / 256, 256>>>(out, N);
}

// round 9
// speedup vs baseline: 1.8654x; 1.0382x over previous
#include <cuda_runtime.h>
#include <cuda_bf16.h>
#include <cuda_fp16.h>
#include <cstdint>

// Problem constants
#define MAXN 50000
#define MAXE 800000
#define IN_DIM 128
#define HD 128
#define ASTRIDE 136               // bf16 elems per smem row (272B, conflict-free ldmatrix)
#define IMG_BYTES (128 * ASTRIDE * 2)           // 34816 B per image
#define QKV_SMEM (3 * IMG_BYTES)                // Ahi, Alo, Bbuf = 104448 B -> 2 blocks/SM

// ---- scratch (static device arrays; no allocation allowed) ----
__device__ float  g_Q[(size_t)MAXN * HD];    // pre-scaled by 0.25, fp32
__device__ __half g_Kh[(size_t)MAXN * HD];   // fp16
__device__ __half g_Vh[(size_t)MAXN * HD];   // fp16
__device__ int    g_deg[MAXN];
__device__ int    g_off[MAXN];               // after scatter: g_off[d] = segment END of d
__device__ int    g_src_sorted[MAXE];
// W^T hi/lo padded images: [matrix][split][n=128 rows][ASTRIDE k-cols]
__device__ __nv_bfloat16 g_Bimg[3][2][128 * ASTRIDE];

__device__ __forceinline__ uint32_t smem_u32(const void* p) {
    uint32_t a;
    asm("{ .reg .u64 t; cvta.to.shared.u64 t, %1; cvt.u32.u64 %0, t; }" : "=r"(a) : "l"(p));
    return a;
}

#define LDSM_X4(r0, r1, r2, r3, addr)                                            \
    asm volatile("ldmatrix.sync.aligned.m8n8.x4.shared.b16 {%0,%1,%2,%3}, [%4];" \
                 : "=r"(r0), "=r"(r1), "=r"(r2), "=r"(r3) : "r"(addr))

#define MMA16816(c, a0, a1, a2, a3, b0, b1)                                      \
    asm volatile("mma.sync.aligned.m16n8k16.row.col.f32.bf16.bf16.f32 "          \
                 "{%0,%1,%2,%3}, {%4,%5,%6,%7}, {%8,%9}, {%0,%1,%2,%3};"         \
                 : "+f"((c)[0]), "+f"((c)[1]), "+f"((c)[2]), "+f"((c)[3])        \
                 : "r"(a0), "r"(a1), "r"(a2), "r"(a3), "r"(b0), "r"(b1))

// ---------------------------------------------------------------------------
// Prepass: W^T hi/lo padded bf16 images. B[n][k] = W[k][n].
// ---------------------------------------------------------------------------
__global__ void wprep_kernel(const float* __restrict__ Wq,
                             const float* __restrict__ Wk,
                             const float* __restrict__ Wv)
{
    int idx = blockIdx.x * blockDim.x + threadIdx.x;
    if (idx >= 3 * 128 * 128) return;
    int m = idx >> 14, rem = idx & 16383, n = rem >> 7, k = rem & 127;
    const float* W = (m == 0) ? Wq : ((m == 1) ? Wk : Wv);
    float w = W[k * 128 + n];
    __nv_bfloat16 hi = __float2bfloat16(w);
    __nv_bfloat16 lo = __float2bfloat16(w - __bfloat162float(hi));
    g_Bimg[m][0][n * ASTRIDE + k] = hi;
    g_Bimg[m][1][n * ASTRIDE + k] = lo;
}

// ---------------------------------------------------------------------------
// Kernel 1: QKV projection via mma.sync bf16 split-GEMM, 2 blocks/SM.
// Block: 128 nodes x 128 cols, 256 threads (8 warps: 4 m-chunks x 2 n-chunks).
// Per matrix m: pass 1 stages Bhi and accumulates Ahi*Bhi + Alo*Bhi;
//              pass 2 stages Blo and accumulates Ahi*Blo.
// ---------------------------------------------------------------------------
__global__ void __launch_bounds__(256, 2) qkv_mma_kernel(
    const float* __restrict__ h,
    const float* __restrict__ bq, const float* __restrict__ bk, const float* __restrict__ bv,
    int N)
{
    extern __shared__ __nv_bfloat16 smem[];
    __nv_bfloat16* Ahi = smem;
    __nv_bfloat16* Alo = smem + 128 * ASTRIDE;
    __nv_bfloat16* Bs  = smem + 2 * 128 * ASTRIDE;   // single B buffer (one split)

    const int tid = threadIdx.x;
    const int lane = tid & 31, warp = tid >> 5;
    const int wm = warp & 3;       // m-chunk: rows [32*wm, 32*wm+32)
    const int wn = warp >> 2;      // n-chunk: cols [64*wn, 64*wn+64)
    const int node0 = blockIdx.x * 128;

    // ---- Stage A: fp32 -> bf16 hi/lo. Thread t: row t>>1, col-half t&1. ----
    {
        const int r = tid >> 1, cb = (tid & 1) * 64;
        const bool valid = (node0 + r) < N;
        const float* hp = h + (size_t)(node0 + r) * IN_DIM + cb;
        __nv_bfloat16* ah = Ahi + r * ASTRIDE + cb;
        __nv_bfloat16* al = Alo + r * ASTRIDE + cb;
#pragma unroll
        for (int i = 0; i < 64; i += 4) {
            float4 v = valid ? *reinterpret_cast<const float4*>(hp + i)
                             : make_float4(0.f, 0.f, 0.f, 0.f);
            __nv_bfloat162 h0 = __floats2bfloat162_rn(v.x, v.y);
            __nv_bfloat162 h1 = __floats2bfloat162_rn(v.z, v.w);
            __nv_bfloat162 l0 = __floats2bfloat162_rn(v.x - __bfloat162float(h0.x),
                                                      v.y - __bfloat162float(h0.y));
            __nv_bfloat162 l1 = __floats2bfloat162_rn(v.z - __bfloat162float(h1.x),
                                                      v.w - __bfloat162float(h1.y));
            *reinterpret_cast<__nv_bfloat162*>(ah + i)     = h0;
            *reinterpret_cast<__nv_bfloat162*>(ah + i + 2) = h1;
            *reinterpret_cast<__nv_bfloat162*>(al + i)     = l0;
            *reinterpret_cast<__nv_bfloat162*>(al + i + 2) = l1;
        }
    }

    const uint32_t uAhi = smem_u32(Ahi), uAlo = smem_u32(Alo);
    const uint32_t uBs  = smem_u32(Bs);

    // A: row = wm*32 + mt*16 + (lane&15); byte += (lane>>4)*16 + kk*32
    const uint32_t aRow = (uint32_t)(wm * 32 + (lane & 15)) * 272u + (uint32_t)(lane >> 4) * 16u;
    // B: n-row = wn*64 + p*16 + ((lane>>4)&1)*8 + (lane&7); byte += ((lane>>3)&1)*16 + kk*32
    const uint32_t bRow = (uint32_t)(wn * 64 + ((lane >> 4) & 1) * 8 + (lane & 7)) * 272u
                        + (uint32_t)((lane >> 3) & 1) * 16u;

    const float* biases[3] = {bq, bk, bv};

    for (int m = 0; m < 3; m++) {
        float acc[2][8][4];
#pragma unroll
        for (int mt = 0; mt < 2; mt++)
#pragma unroll
            for (int nt = 0; nt < 8; nt++)
#pragma unroll
                for (int c = 0; c < 4; c++) acc[mt][nt][c] = 0.f;

        // ======== Pass 1: B = Bhi; products Ahi*Bhi + Alo*Bhi ========
        __syncthreads();
        {
            const float4* sb = reinterpret_cast<const float4*>(g_Bimg[m][0]);
            float4* db = reinterpret_cast<float4*>(Bs);
            for (int i = tid; i < IMG_BYTES / 16; i += 256) db[i] = sb[i];
        }
        __syncthreads();

#pragma unroll
        for (int kk = 0; kk < 8; kk++) {
            const uint32_t kO = (uint32_t)kk * 32u;

            uint32_t ah[2][4], al[2][4];
#pragma unroll
            for (int mt = 0; mt < 2; mt++) {
                const uint32_t ro = aRow + (uint32_t)(mt * 16) * 272u + kO;
                LDSM_X4(ah[mt][0], ah[mt][1], ah[mt][2], ah[mt][3], uAhi + ro);
                LDSM_X4(al[mt][0], al[mt][1], al[mt][2], al[mt][3], uAlo + ro);
            }

            uint32_t bf[8][2];
#pragma unroll
            for (int p = 0; p < 4; p++) {
                const uint32_t ro = bRow + (uint32_t)(p * 16) * 272u + kO;
                LDSM_X4(bf[2 * p][0], bf[2 * p][1], bf[2 * p + 1][0], bf[2 * p + 1][1], uBs + ro);
            }

#pragma unroll
            for (int mt = 0; mt < 2; mt++)
#pragma unroll
                for (int nt = 0; nt < 8; nt++) {
                    MMA16816(acc[mt][nt], ah[mt][0], ah[mt][1], ah[mt][2], ah[mt][3],
                             bf[nt][0], bf[nt][1]);
                    MMA16816(acc[mt][nt], al[mt][0], al[mt][1], al[mt][2], al[mt][3],
                             bf[nt][0], bf[nt][1]);
                }
        }

        // ======== Pass 2: B = Blo; product Ahi*Blo ========
        __syncthreads();
        {
            const float4* sb = reinterpret_cast<const float4*>(g_Bimg[m][1]);
            float4* db = reinterpret_cast<float4*>(Bs);
            for (int i = tid; i < IMG_BYTES / 16; i += 256) db[i] = sb[i];
        }
        __syncthreads();

#pragma unroll
        for (int kk = 0; kk < 8; kk++) {
            const uint32_t kO = (uint32_t)kk * 32u;

            uint32_t ah[2][4];
#pragma unroll
            for (int mt = 0; mt < 2; mt++) {
                const uint32_t ro = aRow + (uint32_t)(mt * 16) * 272u + kO;
                LDSM_X4(ah[mt][0], ah[mt][1], ah[mt][2], ah[mt][3], uAhi + ro);
            }

            uint32_t bf[8][2];
#pragma unroll
            for (int p = 0; p < 4; p++) {
                const uint32_t ro = bRow + (uint32_t)(p * 16) * 272u + kO;
                LDSM_X4(bf[2 * p][0], bf[2 * p][1], bf[2 * p + 1][0], bf[2 * p + 1][1], uBs + ro);
            }

#pragma unroll
            for (int mt = 0; mt < 2; mt++)
#pragma unroll
                for (int nt = 0; nt < 8; nt++)
                    MMA16816(acc[mt][nt], ah[mt][0], ah[mt][1], ah[mt][2], ah[mt][3],
                             bf[nt][0], bf[nt][1]);
        }

        // ---- Epilogue ----
        const float* bb = biases[m];
#pragma unroll
        for (int mt = 0; mt < 2; mt++) {
            const int r0 = node0 + wm * 32 + mt * 16 + (lane >> 2);
#pragma unroll
            for (int nt = 0; nt < 8; nt++) {
                const int col = wn * 64 + nt * 8 + (lane & 3) * 2;
                const float b0 = __ldg(bb + col), b1 = __ldg(bb + col + 1);
                if (m == 0) {
                    if (r0 < N) {
                        float2 o = make_float2((acc[mt][nt][0] + b0) * 0.25f,
                                               (acc[mt][nt][1] + b1) * 0.25f);
                        *reinterpret_cast<float2*>(g_Q + (size_t)r0 * HD + col) = o;
                    }
                    if (r0 + 8 < N) {
                        float2 o = make_float2((acc[mt][nt][2] + b0) * 0.25f,
                                               (acc[mt][nt][3] + b1) * 0.25f);
                        *reinterpret_cast<float2*>(g_Q + (size_t)(r0 + 8) * HD + col) = o;
                    }
                } else {
                    __half* dstp = (m == 1) ? g_Kh : g_Vh;
                    if (r0 < N) {
                        __half2 o = __floats2half2_rn(acc[mt][nt][0] + b0,
                                                      acc[mt][nt][1] + b1);
                        *reinterpret_cast<__half2*>(dstp + (size_t)r0 * HD + col) = o;
                    }
                    if (r0 + 8 < N) {
                        __half2 o = __floats2half2_rn(acc[mt][nt][2] + b0,
                                                      acc[mt][nt][3] + b1);
                        *reinterpret_cast<__half2*>(dstp + (size_t)(r0 + 8) * HD + col) = o;
                    }
                }
            }
        }
    }
}

// ---------------------------------------------------------------------------
// CSR build: hist -> single-block scan -> scatter (atomic bump on g_off)
// ---------------------------------------------------------------------------
__global__ void hist_kernel(const int* __restrict__ dst, int E)
{
    int i = blockIdx.x * blockDim.x + threadIdx.x;
    if (i < E) atomicAdd(&g_deg[dst[i]], 1);
}

__global__ __launch_bounds__(1024) void scan_kernel(int N)
{
    __shared__ int warp_sums[32];
    __shared__ int s_carry;
    const int t = threadIdx.x;
    const int lane = t & 31, wid = t >> 5;
    if (t == 0) s_carry = 0;
    __syncthreads();

    for (int base = 0; base < N; base += 1024) {
        int i = base + t;
        int x = (i < N) ? g_deg[i] : 0;
        int inc = x;
#pragma unroll
        for (int d = 1; d < 32; d <<= 1) {
            int v = __shfl_up_sync(0xffffffffu, inc, d);
            if (lane >= d) inc += v;
        }
        if (lane == 31) warp_sums[wid] = inc;
        __syncthreads();
        if (wid == 0) {
            int ws = warp_sums[lane];
#pragma unroll
            for (int d = 1; d < 32; d <<= 1) {
                int v = __shfl_up_sync(0xffffffffu, ws, d);
                if (lane >= d) ws += v;
            }
            warp_sums[lane] = ws;
        }
        __syncthreads();
        int warp_off = (wid > 0) ? warp_sums[wid - 1] : 0;
        if (i < N) g_off[i] = s_carry + warp_off + inc - x;
        int block_total = warp_sums[31];
        __syncthreads();
        if (t == 0) s_carry += block_total;
        __syncthreads();
    }
}

__global__ void scatter_kernel(const int* __restrict__ src, const int* __restrict__ dst, int E)
{
    int i = blockIdx.x * blockDim.x + threadIdx.x;
    if (i < E) {
        int d = dst[i];
        int p = atomicAdd(&g_off[d], 1);
        g_src_sorted[p] = src[i];
    }
}

// ---------------------------------------------------------------------------
// Kernel 3: warp-per-dst attention over fp16 K/V, unroll-2.
// ---------------------------------------------------------------------------
struct Half4 { __half2 a, b; };

__device__ __forceinline__ float4 h4_to_f4(Half4 x) {
    float2 lo = __half22float2(x.a), hi = __half22float2(x.b);
    return make_float4(lo.x, lo.y, hi.x, hi.y);
}

__global__ void attn_kernel(float* __restrict__ out, int N)
{
    const int lane = threadIdx.x & 31;
    const int w = (blockIdx.x * blockDim.x + threadIdx.x) >> 5;
    if (w >= N) return;

    const int beg = (w == 0) ? 0 : __ldg(&g_off[w - 1]);
    const int end = __ldg(&g_off[w]);

    const float4 q = *reinterpret_cast<const float4*>(g_Q + (size_t)w * HD + lane * 4);

    float4 av = make_float4(0.f, 0.f, 0.f, 0.f);
    float z = 0.f;

    int e = beg;
    for (; e + 2 <= end; e += 2) {
        const int s0 = __ldg(&g_src_sorted[e]);
        const int s1 = __ldg(&g_src_sorted[e + 1]);

        const Half4 K0 = *reinterpret_cast<const Half4*>(g_Kh + (size_t)s0 * HD + lane * 4);
        const Half4 K1 = *reinterpret_cast<const Half4*>(g_Kh + (size_t)s1 * HD + lane * 4);
        const Half4 V0 = *reinterpret_cast<const Half4*>(g_Vh + (size_t)s0 * HD + lane * 4);
        const Half4 V1 = *reinterpret_cast<const Half4*>(g_Vh + (size_t)s1 * HD + lane * 4);

        const float4 k0 = h4_to_f4(K0), k1 = h4_to_f4(K1);
        float sc0 = q.x * k0.x + q.y * k0.y + q.z * k0.z + q.w * k0.w;
        float sc1 = q.x * k1.x + q.y * k1.y + q.z * k1.z + q.w * k1.w;
        sc0 += __shfl_xor_sync(0xffffffffu, sc0, 1);
        sc1 += __shfl_xor_sync(0xffffffffu, sc1, 1);
        sc0 += __shfl_xor_sync(0xffffffffu, sc0, 2);
        sc1 += __shfl_xor_sync(0xffffffffu, sc1, 2);
        sc0 = __expf(fminf(fmaxf(sc0, -5.f), 5.f));
        sc1 = __expf(fminf(fmaxf(sc1, -5.f), 5.f));

        const float4 v0 = h4_to_f4(V0), v1 = h4_to_f4(V1);
        av.x = fmaf(v0.x, sc0, av.x); av.y = fmaf(v0.y, sc0, av.y);
        av.z = fmaf(v0.z, sc0, av.z); av.w = fmaf(v0.w, sc0, av.w);
        av.x = fmaf(v1.x, sc1, av.x); av.y = fmaf(v1.y, sc1, av.y);
        av.z = fmaf(v1.z, sc1, av.z); av.w = fmaf(v1.w, sc1, av.w);
        if ((lane & 3) == 0) z += sc0 + sc1;
    }
    if (e < end) {
        const int s0 = __ldg(&g_src_sorted[e]);
        const Half4 K0 = *reinterpret_cast<const Half4*>(g_Kh + (size_t)s0 * HD + lane * 4);
        const float4 k0 = h4_to_f4(K0);
        float sc0 = q.x * k0.x + q.y * k0.y + q.z * k0.z + q.w * k0.w;
        sc0 += __shfl_xor_sync(0xffffffffu, sc0, 1);
        sc0 += __shfl_xor_sync(0xffffffffu, sc0, 2);
        sc0 = __expf(fminf(fmaxf(sc0, -5.f), 5.f));
        const Half4 V0 = *reinterpret_cast<const Half4*>(g_Vh + (size_t)s0 * HD + lane * 4);
        const float4 v0 = h4_to_f4(V0);
        av.x = fmaf(v0.x, sc0, av.x); av.y = fmaf(v0.y, sc0, av.y);
        av.z = fmaf(v0.z, sc0, av.z); av.w = fmaf(v0.w, sc0, av.w);
        if ((lane & 3) == 0) z += sc0;
    }

    z = __shfl_sync(0xffffffffu, z, lane & ~3);
    const float inv = 1.f / z;

    float4 o;
    o.x = av.x * inv; o.y = av.y * inv; o.z = av.z * inv; o.w = av.w * inv;
    *reinterpret_cast<float4*>(out + (size_t)w * HD + lane * 4) = o;
}

// ---------------------------------------------------------------------------
extern "C" void kernel_launch(void* const* d_in, const int* in_sizes, int n_in,
                              void* d_out, int out_size)
{
    const float* h  = (const float*)d_in[0];
    const int* src  = (const int*)d_in[1];
    const int* dst  = (const int*)d_in[2];
    const float* Wq = (const float*)d_in[3];
    const float* Wk = (const float*)d_in[4];
    const float* Wv = (const float*)d_in[5];
    const float* bq = (const float*)d_in[6];
    const float* bk = (const float*)d_in[7];
    const float* bv = (const float*)d_in[8];
    float* out = (float*)d_out;

    const int N = in_sizes[0] / IN_DIM;
    const int E = in_sizes[1];

    // One-time setup on the uncaptured correctness call
    static cudaStream_t s2 = nullptr;
    static cudaEvent_t evFork = nullptr, evJoin = nullptr;
    static void* degptr = nullptr;
    if (s2 == nullptr) {
        cudaStreamCreateWithFlags(&s2, cudaStreamNonBlocking);
        cudaEventCreateWithFlags(&evFork, cudaEventDisableTiming);
        cudaEventCreateWithFlags(&evJoin, cudaEventDisableTiming);
        cudaGetSymbolAddress(&degptr, g_deg);
        cudaFuncSetAttribute(qkv_mma_kernel, cudaFuncAttributeMaxDynamicSharedMemorySize,
                             QKV_SMEM);
    }

    const int eb = (E + 255) / 256;

    // Fork: CSR build on s2; W prepass + tensor GEMM on the main (capture) stream.
    cudaEventRecord(evFork, 0);
    cudaStreamWaitEvent(s2, evFork, 0);

    cudaMemsetAsync(degptr, 0, (size_t)N * sizeof(int), s2);
    hist_kernel<<<eb, 256, 0, s2>>>(dst, E);
    scan_kernel<<<1, 1024, 0, s2>>>(N);
    scatter_kernel<<<eb, 256, 0, s2>>>(src, dst, E);
    cudaEventRecord(evJoin, s2);

    wprep_kernel<<<(3 * 128 * 128 + 255) / 256, 256>>>(Wq, Wk, Wv);
    qkv_mma_kernel<<<(N + 127) / 128, 256, QKV_SMEM>>>(h, bq, bk, bv, N);

    // Join, then attention (warp per dst node)
    cudaStreamWaitEvent(0, evJoin, 0);
    attn_kernel<<<(N * 32 + 255) / 256, 256>>>(out, N);
}

// round 10
// speedup vs baseline: 1.9735x; 1.0579x over previous
#include <cuda_runtime.h>
#include <cuda_bf16.h>
#include <cuda_fp16.h>
#include <cstdint>

// Problem constants
#define MAXN 50000
#define MAXE 800000
#define IN_DIM 128
#define HD 128
#define ASTRIDE 136               // fp16 elems per smem row (272B, conflict-free ldmatrix)
#define IMG_BYTES (128 * ASTRIDE * 2)           // 34816 B per image
#define QKV_SMEM (3 * IMG_BYTES)                // Ahi, Alo, B = 104448 B -> 2 blocks/SM

// ---- scratch (static device arrays; no allocation allowed) ----
__device__ float  g_Q[(size_t)MAXN * HD];    // pre-scaled by 0.25, fp32
__device__ __half g_Kh[(size_t)MAXN * HD];   // fp16
__device__ __half g_Vh[(size_t)MAXN * HD];   // fp16
__device__ int    g_deg[MAXN];
__device__ int    g_off[MAXN];               // after scatter: g_off[d] = segment END of d
__device__ int    g_src_sorted[MAXE];
// W^T fp16 padded images: [matrix][n=128 rows][ASTRIDE k-cols]
__device__ __half g_Bimg[3][128 * ASTRIDE];

__device__ __forceinline__ uint32_t smem_u32(const void* p) {
    uint32_t a;
    asm("{ .reg .u64 t; cvta.to.shared.u64 t, %1; cvt.u32.u64 %0, t; }" : "=r"(a) : "l"(p));
    return a;
}

#define LDSM_X4(r0, r1, r2, r3, addr)                                            \
    asm volatile("ldmatrix.sync.aligned.m8n8.x4.shared.b16 {%0,%1,%2,%3}, [%4];" \
                 : "=r"(r0), "=r"(r1), "=r"(r2), "=r"(r3) : "r"(addr))

#define MMA16816F(c, a0, a1, a2, a3, b0, b1)                                     \
    asm volatile("mma.sync.aligned.m16n8k16.row.col.f32.f16.f16.f32 "            \
                 "{%0,%1,%2,%3}, {%4,%5,%6,%7}, {%8,%9}, {%0,%1,%2,%3};"         \
                 : "+f"((c)[0]), "+f"((c)[1]), "+f"((c)[2]), "+f"((c)[3])        \
                 : "r"(a0), "r"(a1), "r"(a2), "r"(a3), "r"(b0), "r"(b1))

// ---------------------------------------------------------------------------
// Prepass: W^T fp16 padded images. B[n][k] = W[k][n].
// ---------------------------------------------------------------------------
__global__ void wprep_kernel(const float* __restrict__ Wq,
                             const float* __restrict__ Wk,
                             const float* __restrict__ Wv)
{
    int idx = blockIdx.x * blockDim.x + threadIdx.x;
    if (idx >= 3 * 128 * 128) return;
    int m = idx >> 14, rem = idx & 16383, n = rem >> 7, k = rem & 127;
    const float* W = (m == 0) ? Wq : ((m == 1) ? Wk : Wv);
    g_Bimg[m][n * ASTRIDE + k] = __float2half_rn(W[k * 128 + n]);
}

// ---------------------------------------------------------------------------
// Kernel 1: QKV projection via mma.sync fp16 2-product split-GEMM.
// Block: 128 nodes x 128 cols, 256 threads (8 warps: 4 m-chunks x 2 n-chunks).
// A = Ahi + Alo (fp16 hi + fp16 residual); B = Bhi (fp16). One B staging and
// one compute pass per matrix: acc = Ahi*B + Alo*B (error = A*(B-Bhi) ~1.4e-4).
// ---------------------------------------------------------------------------
__global__ void __launch_bounds__(256, 2) qkv_mma_kernel(
    const float* __restrict__ h,
    const float* __restrict__ bq, const float* __restrict__ bk, const float* __restrict__ bv,
    int N)
{
    extern __shared__ __half smem[];
    __half* Ahi = smem;
    __half* Alo = smem + 128 * ASTRIDE;
    __half* Bs  = smem + 2 * 128 * ASTRIDE;

    const int tid = threadIdx.x;
    const int lane = tid & 31, warp = tid >> 5;
    const int wm = warp & 3;       // m-chunk: rows [32*wm, 32*wm+32)
    const int wn = warp >> 2;      // n-chunk: cols [64*wn, 64*wn+64)
    const int node0 = blockIdx.x * 128;

    // ---- Stage A: fp32 -> fp16 hi + residual. Thread t: row t>>1, col-half t&1. ----
    {
        const int r = tid >> 1, cb = (tid & 1) * 64;
        const bool valid = (node0 + r) < N;
        const float* hp = h + (size_t)(node0 + r) * IN_DIM + cb;
        __half* ah = Ahi + r * ASTRIDE + cb;
        __half* al = Alo + r * ASTRIDE + cb;
#pragma unroll
        for (int i = 0; i < 64; i += 4) {
            float4 v = valid ? *reinterpret_cast<const float4*>(hp + i)
                             : make_float4(0.f, 0.f, 0.f, 0.f);
            __half hx = __float2half_rn(v.x), hy = __float2half_rn(v.y);
            __half hz = __float2half_rn(v.z), hw = __float2half_rn(v.w);
            __half lx = __float2half_rn(v.x - __half2float(hx));
            __half ly = __float2half_rn(v.y - __half2float(hy));
            __half lz = __float2half_rn(v.z - __half2float(hz));
            __half lw = __float2half_rn(v.w - __half2float(hw));
            *reinterpret_cast<__half2*>(ah + i)     = __halves2half2(hx, hy);
            *reinterpret_cast<__half2*>(ah + i + 2) = __halves2half2(hz, hw);
            *reinterpret_cast<__half2*>(al + i)     = __halves2half2(lx, ly);
            *reinterpret_cast<__half2*>(al + i + 2) = __halves2half2(lz, lw);
        }
    }

    const uint32_t uAhi = smem_u32(Ahi), uAlo = smem_u32(Alo);
    const uint32_t uBs  = smem_u32(Bs);

    // A: row = wm*32 + mt*16 + (lane&15); byte += (lane>>4)*16 + kk*32
    const uint32_t aRow = (uint32_t)(wm * 32 + (lane & 15)) * 272u + (uint32_t)(lane >> 4) * 16u;
    // B: n-row = wn*64 + p*16 + ((lane>>4)&1)*8 + (lane&7); byte += ((lane>>3)&1)*16 + kk*32
    const uint32_t bRow = (uint32_t)(wn * 64 + ((lane >> 4) & 1) * 8 + (lane & 7)) * 272u
                        + (uint32_t)((lane >> 3) & 1) * 16u;

    const float* biases[3] = {bq, bk, bv};

    for (int m = 0; m < 3; m++) {
        // ---- Stage B (single fp16 image of matrix m) ----
        __syncthreads();
        {
            const float4* sb = reinterpret_cast<const float4*>(g_Bimg[m]);
            float4* db = reinterpret_cast<float4*>(Bs);
            for (int i = tid; i < IMG_BYTES / 16; i += 256) db[i] = sb[i];
        }
        __syncthreads();

        float acc[2][8][4];
#pragma unroll
        for (int mt = 0; mt < 2; mt++)
#pragma unroll
            for (int nt = 0; nt < 8; nt++)
#pragma unroll
                for (int c = 0; c < 4; c++) acc[mt][nt][c] = 0.f;

#pragma unroll
        for (int kk = 0; kk < 8; kk++) {
            const uint32_t kO = (uint32_t)kk * 32u;

            uint32_t ah[2][4], al[2][4];
#pragma unroll
            for (int mt = 0; mt < 2; mt++) {
                const uint32_t ro = aRow + (uint32_t)(mt * 16) * 272u + kO;
                LDSM_X4(ah[mt][0], ah[mt][1], ah[mt][2], ah[mt][3], uAhi + ro);
                LDSM_X4(al[mt][0], al[mt][1], al[mt][2], al[mt][3], uAlo + ro);
            }

            uint32_t bf[8][2];
#pragma unroll
            for (int p = 0; p < 4; p++) {
                const uint32_t ro = bRow + (uint32_t)(p * 16) * 272u + kO;
                LDSM_X4(bf[2 * p][0], bf[2 * p][1], bf[2 * p + 1][0], bf[2 * p + 1][1], uBs + ro);
            }

#pragma unroll
            for (int mt = 0; mt < 2; mt++)
#pragma unroll
                for (int nt = 0; nt < 8; nt++) {
                    MMA16816F(acc[mt][nt], ah[mt][0], ah[mt][1], ah[mt][2], ah[mt][3],
                              bf[nt][0], bf[nt][1]);
                    MMA16816F(acc[mt][nt], al[mt][0], al[mt][1], al[mt][2], al[mt][3],
                              bf[nt][0], bf[nt][1]);
                }
        }

        // ---- Epilogue ----
        const float* bb = biases[m];
#pragma unroll
        for (int mt = 0; mt < 2; mt++) {
            const int r0 = node0 + wm * 32 + mt * 16 + (lane >> 2);
#pragma unroll
            for (int nt = 0; nt < 8; nt++) {
                const int col = wn * 64 + nt * 8 + (lane & 3) * 2;
                const float b0 = __ldg(bb + col), b1 = __ldg(bb + col + 1);
                if (m == 0) {
                    if (r0 < N) {
                        float2 o = make_float2((acc[mt][nt][0] + b0) * 0.25f,
                                               (acc[mt][nt][1] + b1) * 0.25f);
                        *reinterpret_cast<float2*>(g_Q + (size_t)r0 * HD + col) = o;
                    }
                    if (r0 + 8 < N) {
                        float2 o = make_float2((acc[mt][nt][2] + b0) * 0.25f,
                                               (acc[mt][nt][3] + b1) * 0.25f);
                        *reinterpret_cast<float2*>(g_Q + (size_t)(r0 + 8) * HD + col) = o;
                    }
                } else {
                    __half* dstp = (m == 1) ? g_Kh : g_Vh;
                    if (r0 < N) {
                        __half2 o = __floats2half2_rn(acc[mt][nt][0] + b0,
                                                      acc[mt][nt][1] + b1);
                        *reinterpret_cast<__half2*>(dstp + (size_t)r0 * HD + col) = o;
                    }
                    if (r0 + 8 < N) {
                        __half2 o = __floats2half2_rn(acc[mt][nt][2] + b0,
                                                      acc[mt][nt][3] + b1);
                        *reinterpret_cast<__half2*>(dstp + (size_t)(r0 + 8) * HD + col) = o;
                    }
                }
            }
        }
    }
}

// ---------------------------------------------------------------------------
// CSR build: hist -> single-block scan -> scatter (atomic bump on g_off)
// ---------------------------------------------------------------------------
__global__ void hist_kernel(const int* __restrict__ dst, int E)
{
    int i = blockIdx.x * blockDim.x + threadIdx.x;
    if (i < E) atomicAdd(&g_deg[dst[i]], 1);
}

__global__ __launch_bounds__(1024) void scan_kernel(int N)
{
    __shared__ int warp_sums[32];
    __shared__ int s_carry;
    const int t = threadIdx.x;
    const int lane = t & 31, wid = t >> 5;
    if (t == 0) s_carry = 0;
    __syncthreads();

    for (int base = 0; base < N; base += 1024) {
        int i = base + t;
        int x = (i < N) ? g_deg[i] : 0;
        int inc = x;
#pragma unroll
        for (int d = 1; d < 32; d <<= 1) {
            int v = __shfl_up_sync(0xffffffffu, inc, d);
            if (lane >= d) inc += v;
        }
        if (lane == 31) warp_sums[wid] = inc;
        __syncthreads();
        if (wid == 0) {
            int ws = warp_sums[lane];
#pragma unroll
            for (int d = 1; d < 32; d <<= 1) {
                int v = __shfl_up_sync(0xffffffffu, ws, d);
                if (lane >= d) ws += v;
            }
            warp_sums[lane] = ws;
        }
        __syncthreads();
        int warp_off = (wid > 0) ? warp_sums[wid - 1] : 0;
        if (i < N) g_off[i] = s_carry + warp_off + inc - x;
        int block_total = warp_sums[31];
        __syncthreads();
        if (t == 0) s_carry += block_total;
        __syncthreads();
    }
}

__global__ void scatter_kernel(const int* __restrict__ src, const int* __restrict__ dst, int E)
{
    int i = blockIdx.x * blockDim.x + threadIdx.x;
    if (i < E) {
        int d = dst[i];
        int p = atomicAdd(&g_off[d], 1);
        g_src_sorted[p] = src[i];
    }
}

// ---------------------------------------------------------------------------
// Kernel 3: warp-per-dst attention over fp16 K/V, unroll-4.
// Lane l owns dims [4l,4l+4) => head l>>2. Q fp32.
// ---------------------------------------------------------------------------
struct Half4 { __half2 a, b; };

__device__ __forceinline__ float4 h4_to_f4(Half4 x) {
    float2 lo = __half22float2(x.a), hi = __half22float2(x.b);
    return make_float4(lo.x, lo.y, hi.x, hi.y);
}

__global__ void attn_kernel(float* __restrict__ out, int N)
{
    const int lane = threadIdx.x & 31;
    const int w = (blockIdx.x * blockDim.x + threadIdx.x) >> 5;
    if (w >= N) return;

    const int beg = (w == 0) ? 0 : __ldg(&g_off[w - 1]);
    const int end = __ldg(&g_off[w]);

    const float4 q = *reinterpret_cast<const float4*>(g_Q + (size_t)w * HD + lane * 4);

    float4 av = make_float4(0.f, 0.f, 0.f, 0.f);
    float z = 0.f;

    int e = beg;
    for (; e + 4 <= end; e += 4) {
        int s[4];
#pragma unroll
        for (int j = 0; j < 4; j++) s[j] = __ldg(&g_src_sorted[e + j]);

        Half4 K[4], V[4];
#pragma unroll
        for (int j = 0; j < 4; j++) {
            K[j] = *reinterpret_cast<const Half4*>(g_Kh + (size_t)s[j] * HD + lane * 4);
            V[j] = *reinterpret_cast<const Half4*>(g_Vh + (size_t)s[j] * HD + lane * 4);
        }

        float sc[4];
#pragma unroll
        for (int j = 0; j < 4; j++) {
            const float4 k = h4_to_f4(K[j]);
            sc[j] = q.x * k.x + q.y * k.y + q.z * k.z + q.w * k.w;
        }
#pragma unroll
        for (int j = 0; j < 4; j++) sc[j] += __shfl_xor_sync(0xffffffffu, sc[j], 1);
#pragma unroll
        for (int j = 0; j < 4; j++) sc[j] += __shfl_xor_sync(0xffffffffu, sc[j], 2);
#pragma unroll
        for (int j = 0; j < 4; j++) sc[j] = __expf(fminf(fmaxf(sc[j], -5.f), 5.f));

#pragma unroll
        for (int j = 0; j < 4; j++) {
            const float4 v = h4_to_f4(V[j]);
            av.x = fmaf(v.x, sc[j], av.x); av.y = fmaf(v.y, sc[j], av.y);
            av.z = fmaf(v.z, sc[j], av.z); av.w = fmaf(v.w, sc[j], av.w);
        }
        if ((lane & 3) == 0) z += (sc[0] + sc[1]) + (sc[2] + sc[3]);
    }
    for (; e < end; e++) {
        const int s0 = __ldg(&g_src_sorted[e]);
        const Half4 K0 = *reinterpret_cast<const Half4*>(g_Kh + (size_t)s0 * HD + lane * 4);
        const float4 k0 = h4_to_f4(K0);
        float sc0 = q.x * k0.x + q.y * k0.y + q.z * k0.z + q.w * k0.w;
        sc0 += __shfl_xor_sync(0xffffffffu, sc0, 1);
        sc0 += __shfl_xor_sync(0xffffffffu, sc0, 2);
        sc0 = __expf(fminf(fmaxf(sc0, -5.f), 5.f));
        const Half4 V0 = *reinterpret_cast<const Half4*>(g_Vh + (size_t)s0 * HD + lane * 4);
        const float4 v0 = h4_to_f4(V0);
        av.x = fmaf(v0.x, sc0, av.x); av.y = fmaf(v0.y, sc0, av.y);
        av.z = fmaf(v0.z, sc0, av.z); av.w = fmaf(v0.w, sc0, av.w);
        if ((lane & 3) == 0) z += sc0;
    }

    z = __shfl_sync(0xffffffffu, z, lane & ~3);
    const float inv = 1.f / z;

    float4 o;
    o.x = av.x * inv; o.y = av.y * inv; o.z = av.z * inv; o.w = av.w * inv;
    *reinterpret_cast<float4*>(out + (size_t)w * HD + lane * 4) = o;
}

// ---------------------------------------------------------------------------
extern "C" void kernel_launch(void* const* d_in, const int* in_sizes, int n_in,
                              void* d_out, int out_size)
{
    const float* h  = (const float*)d_in[0];
    const int* src  = (const int*)d_in[1];
    const int* dst  = (const int*)d_in[2];
    const float* Wq = (const float*)d_in[3];
    const float* Wk = (const float*)d_in[4];
    const float* Wv = (const float*)d_in[5];
    const float* bq = (const float*)d_in[6];
    const float* bk = (const float*)d_in[7];
    const float* bv = (const float*)d_in[8];
    float* out = (float*)d_out;

    const int N = in_sizes[0] / IN_DIM;
    const int E = in_sizes[1];

    // One-time setup on the uncaptured correctness call
    static cudaStream_t s2 = nullptr;
    static cudaEvent_t evFork = nullptr, evJoin = nullptr;
    static void* degptr = nullptr;
    if (s2 == nullptr) {
        cudaStreamCreateWithFlags(&s2, cudaStreamNonBlocking);
        cudaEventCreateWithFlags(&evFork, cudaEventDisableTiming);
        cudaEventCreateWithFlags(&evJoin, cudaEventDisableTiming);
        cudaGetSymbolAddress(&degptr, g_deg);
        cudaFuncSetAttribute(qkv_mma_kernel, cudaFuncAttributeMaxDynamicSharedMemorySize,
                             QKV_SMEM);
    }

    const int eb = (E + 255) / 256;

    // Fork: CSR build on s2; W prepass + tensor GEMM on the main (capture) stream.
    cudaEventRecord(evFork, 0);
    cudaStreamWaitEvent(s2, evFork, 0);

    cudaMemsetAsync(degptr, 0, (size_t)N * sizeof(int), s2);
    hist_kernel<<<eb, 256, 0, s2>>>(dst, E);
    scan_kernel<<<1, 1024, 0, s2>>>(N);
    scatter_kernel<<<eb, 256, 0, s2>>>(src, dst, E);
    cudaEventRecord(evJoin, s2);

    wprep_kernel<<<(3 * 128 * 128 + 255) / 256, 256>>>(Wq, Wk, Wv);
    qkv_mma_kernel<<<(N + 127) / 128, 256, QKV_SMEM>>>(h, bq, bk, bv, N);

    // Join, then attention (warp per dst node)
    cudaStreamWaitEvent(0, evJoin, 0);
    attn_kernel<<<(N * 32 + 255) / 256, 256>>>(out, N);
}